// round 6
// baseline (speedup 1.0000x reference)
#include <cuda_runtime.h>
#include <cuda_bf16.h>
#include <math.h>
#include <stdint.h>

// ---------------- problem constants ----------------
#define BATCH 8
#define DIMC 128
#define HGT 64
#define WID 64
#define HW 4096
#define M_TOT 32768       // BATCH*HGT*WID
#define K3 384

// ---------------- scratch ----------------
__device__ float g_xcat[M_TOT * K3];
__device__ float g_x[M_TOT * DIMC];
__device__ float g_gxh[M_TOT * K3];
__device__ float g_gxw[M_TOT * K3];
__device__ float g_oh[M_TOT * DIMC];
__device__ float g_ow[M_TOT * DIMC];

// ======================================================================
// helpers
// ======================================================================
__device__ __forceinline__ uint32_t smem_u32(const void* p) {
    uint32_t a;
    asm("{ .reg .u64 t; cvta.to.shared.u64 t, %1; cvt.u32.u64 %0, t; }"
        : "=r"(a) : "l"(p));
    return a;
}

__device__ __forceinline__ void ldsm4(uint32_t* r, uint32_t addr) {
    asm volatile("ldmatrix.sync.aligned.m8n8.x4.shared.b16 {%0,%1,%2,%3}, [%4];"
                 : "=r"(r[0]), "=r"(r[1]), "=r"(r[2]), "=r"(r[3]) : "r"(addr));
}

__device__ __forceinline__ void mma16816(float* c, const uint32_t* a, const uint32_t* b) {
    asm volatile(
        "mma.sync.aligned.m16n8k16.row.col.f32.bf16.bf16.f32 "
        "{%0,%1,%2,%3}, {%4,%5,%6,%7}, {%8,%9}, {%0,%1,%2,%3};"
        : "+f"(c[0]), "+f"(c[1]), "+f"(c[2]), "+f"(c[3])
        : "r"(a[0]), "r"(a[1]), "r"(a[2]), "r"(a[3]), "r"(b[0]), "r"(b[1]));
}

// convert float4 -> bf16 hi pair + bf16 lo-residual pair
__device__ __forceinline__ void cvt4(float4 v, uint2& hi, uint2& lo) {
    unsigned short b0 = __bfloat16_as_ushort(__float2bfloat16(v.x));
    unsigned short b1 = __bfloat16_as_ushort(__float2bfloat16(v.y));
    unsigned short b2 = __bfloat16_as_ushort(__float2bfloat16(v.z));
    unsigned short b3 = __bfloat16_as_ushort(__float2bfloat16(v.w));
    hi.x = ((uint32_t)b1 << 16) | (uint32_t)b0;
    hi.y = ((uint32_t)b3 << 16) | (uint32_t)b2;
    float r0 = v.x - __uint_as_float((uint32_t)b0 << 16);
    float r1 = v.y - __uint_as_float((uint32_t)b1 << 16);
    float r2 = v.z - __uint_as_float((uint32_t)b2 << 16);
    float r3 = v.w - __uint_as_float((uint32_t)b3 << 16);
    unsigned short c0 = __bfloat16_as_ushort(__float2bfloat16(r0));
    unsigned short c1 = __bfloat16_as_ushort(__float2bfloat16(r1));
    unsigned short c2 = __bfloat16_as_ushort(__float2bfloat16(r2));
    unsigned short c3 = __bfloat16_as_ushort(__float2bfloat16(r3));
    lo.x = ((uint32_t)c1 << 16) | (uint32_t)c0;
    lo.y = ((uint32_t)c3 << 16) | (uint32_t)c2;
}

// ======================================================================
// bf16x3 warp-MMA NT GEMM (coalesced staging)
// ======================================================================
#define SA_STRIDE 136
#define MMA_SMEM (104448)

template<int KSLABS, int NTILES, int EPI>
__device__ void mma_core(const float* __restrict__ A0, int lda,
                         const float* __restrict__ B0, int ldb,
                         const float* __restrict__ p0, const float* __restrict__ p1,
                         float* __restrict__ C0, int ldc)
{
    extern __shared__ char smraw[];
    __nv_bfloat16* sa_hi = (__nv_bfloat16*)(smraw);
    __nv_bfloat16* sa_lo = (__nv_bfloat16*)(smraw + 34816);
    __nv_bfloat16* sb_hi = (__nv_bfloat16*)(smraw + 69632);
    __nv_bfloat16* sb_lo = (__nv_bfloat16*)(smraw + 87040);
    const uint32_t sbase = smem_u32(smraw);
    const uint32_t u_sa_hi = sbase;
    const uint32_t u_sa_lo = sbase + 34816;
    const uint32_t u_sb_hi = sbase + 69632;
    const uint32_t u_sb_lo = sbase + 87040;

    const int tid  = threadIdx.x;
    const int wid  = tid >> 5;
    const int lane = tid & 31;
    const int wm = wid >> 1;
    const int wn = wid & 1;
    const int gid = lane >> 2, tig = lane & 3;
    const int col4 = (tid & 31) * 4;
    const int rbase = tid >> 5;

#pragma unroll 1
    for (int nt = 0; nt < NTILES; nt++) {
        float acc[2][4][4];
#pragma unroll
        for (int i = 0; i < 2; i++)
#pragma unroll
            for (int j = 0; j < 4; j++)
#pragma unroll
                for (int e = 0; e < 4; e++) acc[i][j][e] = 0.f;

#pragma unroll 1
        for (int s = 0; s < KSLABS; s++) {
            __syncthreads();
            if (nt == 0 || KSLABS > 1) {
#pragma unroll
                for (int j = 0; j < 16; j++) {
                    int r = rbase + 8 * j;
                    float4 v = *(const float4*)(A0 + (size_t)r * lda + s * 128 + col4);
                    uint2 hi, lo; cvt4(v, hi, lo);
                    *(uint2*)(sa_hi + r * SA_STRIDE + col4) = hi;
                    *(uint2*)(sa_lo + r * SA_STRIDE + col4) = lo;
                }
            }
            {
#pragma unroll
                for (int j = 0; j < 8; j++) {
                    int r = rbase + 8 * j;
                    float4 v = *(const float4*)(B0 + (size_t)(nt * 64 + r) * ldb + s * 128 + col4);
                    uint2 hi, lo; cvt4(v, hi, lo);
                    *(uint2*)(sb_hi + r * SA_STRIDE + col4) = hi;
                    *(uint2*)(sb_lo + r * SA_STRIDE + col4) = lo;
                }
            }
            __syncthreads();

#pragma unroll
            for (int ch = 0; ch < 8; ch++) {
                const int k = ch * 16;
                uint32_t ah[2][4], al[2][4];
#pragma unroll
                for (int i = 0; i < 2; i++) {
                    uint32_t off = (uint32_t)(((wm*32 + i*16 + (lane & 15)) * SA_STRIDE
                                               + k + ((lane >> 4) << 3)) * 2);
                    ldsm4(ah[i], u_sa_hi + off);
                    ldsm4(al[i], u_sa_lo + off);
                }
                uint32_t bh[4][2], bl[4][2];
#pragma unroll
                for (int nb = 0; nb < 2; nb++) {
                    int row = wn*32 + nb*16 + (lane & 7) + ((lane >> 4) << 3);
                    int col = k + ((lane >> 3) & 1) * 8;
                    uint32_t off = (uint32_t)((row * SA_STRIDE + col) * 2);
                    uint32_t r[4];
                    ldsm4(r, u_sb_hi + off);
                    bh[2*nb][0] = r[0]; bh[2*nb][1] = r[1];
                    bh[2*nb+1][0] = r[2]; bh[2*nb+1][1] = r[3];
                    ldsm4(r, u_sb_lo + off);
                    bl[2*nb][0] = r[0]; bl[2*nb][1] = r[1];
                    bl[2*nb+1][0] = r[2]; bl[2*nb+1][1] = r[3];
                }
#pragma unroll
                for (int i = 0; i < 2; i++)
#pragma unroll
                    for (int j = 0; j < 4; j++) {
                        mma16816(acc[i][j], ah[i], bh[j]);
                        mma16816(acc[i][j], ah[i], bl[j]);
                        mma16816(acc[i][j], al[i], bh[j]);
                    }
            }
        }

#pragma unroll
        for (int i = 0; i < 2; i++) {
            int mrow = wm*32 + i*16 + gid;
#pragma unroll
            for (int j = 0; j < 4; j++) {
                int ncol = nt*64 + wn*32 + j*8 + tig*2;
                float2 q0 = *(const float2*)(p0 + ncol);
                float2 q1 = (EPI == 0) ? *(const float2*)(p1 + ncol)
                                       : make_float2(0.f, 0.f);
                float v0, v1, v2, v3;
                if (EPI == 0) {
                    v0 = fmaxf(fmaf(acc[i][j][0], q0.x, q1.x), 0.f);
                    v1 = fmaxf(fmaf(acc[i][j][1], q0.y, q1.y), 0.f);
                    v2 = fmaxf(fmaf(acc[i][j][2], q0.x, q1.x), 0.f);
                    v3 = fmaxf(fmaf(acc[i][j][3], q0.y, q1.y), 0.f);
                } else {
                    v0 = acc[i][j][0] + q0.x;
                    v1 = acc[i][j][1] + q0.y;
                    v2 = acc[i][j][2] + q0.x;
                    v3 = acc[i][j][3] + q0.y;
                }
                *(float2*)(C0 + (size_t)mrow * ldc + ncol) = make_float2(v0, v1);
                *(float2*)(C0 + (size_t)(mrow + 8) * ldc + ncol) = make_float2(v2, v3);
            }
        }
    }
}

__global__ void __launch_bounds__(256)
mma_proj_kernel(const float* __restrict__ xcat, const float* __restrict__ piw,
                const float* __restrict__ pisc, const float* __restrict__ pish,
                float* __restrict__ x)
{
    mma_core<3, 2, 0>(xcat + (size_t)blockIdx.x * 128 * K3, K3,
                      piw, K3, pisc, pish,
                      x + (size_t)blockIdx.x * 128 * DIMC, DIMC);
}

__global__ void __launch_bounds__(256)
mma_gx_kernel(const float* __restrict__ x,
              const float* __restrict__ wih_h, const float* __restrict__ bih_h,
              const float* __restrict__ wih_w, const float* __restrict__ bih_w,
              float* __restrict__ gxh, float* __restrict__ gxw)
{
    const float* B    = blockIdx.y ? wih_w : wih_h;
    const float* bias = blockIdx.y ? bih_w : bih_h;
    float* out        = blockIdx.y ? gxw : gxh;
    mma_core<1, 6, 1>(x + (size_t)blockIdx.x * 128 * DIMC, DIMC,
                      B, DIMC, bias, nullptr,
                      out + (size_t)blockIdx.x * 128 * K3, K3);
}

// ======================================================================
// resize + concat, coalesced: one block per (b,h) row, lanes along w.
// ======================================================================
__global__ void __launch_bounds__(256)
resize_concat_kernel(const float* __restrict__ l,
                     const float* __restrict__ mid,
                     const float* __restrict__ s,
                     float* __restrict__ xcat)
{
    __shared__ float st[64 * 65];
    const int bh = blockIdx.x;          // b*64 + h
    const int b = bh >> 6, h = bh & 63;
    const int tid = threadIdx.x;
    const int wq = tid & 63;
    const int cl = tid >> 6;

    int ljh[4]; float lwh[4];
    int ljw[4]; float lww[4];
    {
        float sum = 0.f;
#pragma unroll
        for (int t = 0; t < 4; t++) {
            int jj = 2*h - 1 + t;
            float r = (t == 0 || t == 3) ? 0.25f : 0.75f;
            bool ok = (jj >= 0 && jj < 128);
            ljh[t] = ok ? jj : 0;
            lwh[t] = ok ? r : 0.f;
            sum += lwh[t];
        }
        float inv = 1.f / sum;
#pragma unroll
        for (int t = 0; t < 4; t++) lwh[t] *= inv;
    }
    {
        float sum = 0.f;
#pragma unroll
        for (int t = 0; t < 4; t++) {
            int jj = 2*wq - 1 + t;
            float r = (t == 0 || t == 3) ? 0.25f : 0.75f;
            bool ok = (jj >= 0 && jj < 128);
            ljw[t] = ok ? jj : 0;
            lww[t] = ok ? r : 0.f;
            sum += lww[t];
        }
        float inv = 1.f / sum;
#pragma unroll
        for (int t = 0; t < 4; t++) lww[t] *= inv;
    }
    int sjh[2]; float swh[2];
    int sjw[2]; float sww[2];
    {
        float p = 0.5f*h - 0.25f;
        int j0 = (int)floorf(p);
        float f = p - (float)j0;
        bool o0 = (j0 >= 0 && j0 < 32), o1 = (j0+1 >= 0 && j0+1 < 32);
        swh[0] = o0 ? (1.f - f) : 0.f; sjh[0] = o0 ? j0 : 0;
        swh[1] = o1 ? f : 0.f;         sjh[1] = o1 ? (j0+1) : 0;
        float inv = 1.f / (swh[0] + swh[1]);
        swh[0] *= inv; swh[1] *= inv;
    }
    {
        float p = 0.5f*wq - 0.25f;
        int j0 = (int)floorf(p);
        float f = p - (float)j0;
        bool o0 = (j0 >= 0 && j0 < 32), o1 = (j0+1 >= 0 && j0+1 < 32);
        sww[0] = o0 ? (1.f - f) : 0.f; sjw[0] = o0 ? j0 : 0;
        sww[1] = o1 ? f : 0.f;         sjw[1] = o1 ? (j0+1) : 0;
        float inv = 1.f / (sww[0] + sww[1]);
        sww[0] *= inv; sww[1] *= inv;
    }

    const int ww = tid >> 2;
    const int c0 = (tid & 3) * 16;

#pragma unroll 1
    for (int chunk = 0; chunk < 6; chunk++) {
        const int cbase = chunk * 64;
        if (chunk < 2) {
#pragma unroll 4
            for (int i = 0; i < 16; i++) {
                int c = cbase + cl + 4*i;
                const float* lp = l + ((size_t)(b*128 + c) << 14);
                float v = 0.f;
#pragma unroll
                for (int a = 0; a < 4; a++) {
                    const float* row = lp + (ljh[a] << 7);
                    float ra = lww[0]*row[ljw[0]] + lww[1]*row[ljw[1]]
                             + lww[2]*row[ljw[2]] + lww[3]*row[ljw[3]];
                    v = fmaf(lwh[a], ra, v);
                }
                st[(cl + 4*i) * 65 + wq] = v;
            }
        } else if (chunk < 4) {
#pragma unroll 4
            for (int i = 0; i < 16; i++) {
                int c = cbase - 128 + cl + 4*i;
                st[(cl + 4*i) * 65 + wq] =
                    mid[((size_t)(b*128 + c) << 12) + (h << 6) + wq];
            }
        } else {
#pragma unroll 4
            for (int i = 0; i < 16; i++) {
                int c = cbase - 256 + cl + 4*i;
                const float* sp = s + ((size_t)(b*128 + c) << 10);
                const float* r0 = sp + (sjh[0] << 5);
                const float* r1 = sp + (sjh[1] << 5);
                float v = swh[0]*(sww[0]*r0[sjw[0]] + sww[1]*r0[sjw[1]])
                        + swh[1]*(sww[0]*r1[sjw[0]] + sww[1]*r1[sjw[1]]);
                st[(cl + 4*i) * 65 + wq] = v;
            }
        }
        __syncthreads();
        float* dst = xcat + (size_t)(bh*64 + ww) * K3 + cbase + c0;
#pragma unroll
        for (int j = 0; j < 4; j++) {
            int cc = c0 + 4*j;
            float4 v = make_float4(st[(cc+0)*65 + ww], st[(cc+1)*65 + ww],
                                   st[(cc+2)*65 + ww], st[(cc+3)*65 + ww]);
            *(float4*)(dst + 4*j) = v;
        }
        __syncthreads();
    }
}

// ======================================================================
// Scan kernel: 128 blocks x 768 threads.
// Thread (g = tid>>1, kh = tid&1) owns k-half kh of gate-row g.
// Weights in smem [384][2][68] (bank-conflict-free, float4-aligned).
// Pure-FMA phase writes raw sums to sg; tail threads (tid<256, 4 seqs each)
// add gx + bias, apply nonlinearity, update h.
// ======================================================================
#define SCAN_SMEM ((384*136 + 384*9 + 128*8) * 4)

#define FMA2(acc, a, b) \
    asm volatile("fma.rn.f32x2 %0, %1, %2, %0;" : "+l"(acc) : "l"(a), "l"(b))
#define PACK2(d, f) \
    asm volatile("mov.b64 %0, {%1, %1};" : "=l"(d) : "r"(__float_as_uint(f)))

__global__ void __launch_bounds__(768, 1)
scan_kernel(const float* __restrict__ whh_h,
            const float* __restrict__ bhh_h,
            const float* __restrict__ whh_w,
            const float* __restrict__ bhh_w,
            const float* __restrict__ gxh,
            const float* __restrict__ gxw,
            float* __restrict__ ohp,
            float* __restrict__ owp)
{
    extern __shared__ float sm[];
    float* whh2 = sm;                     // [384][2][68]
    float* sg   = sm + 384*136;           // [384][9]
    float* hbuf = sm + 384*136 + 384*9;   // [128][8]

    const int dir = blockIdx.x >> 6;
    const int sub = blockIdx.x & 63;
    const int b   = sub >> 3;
    const int q0  = (sub & 7) << 3;

    const float* whh = dir ? whh_w : whh_h;
    const float* bhh = dir ? bhh_w : bhh_h;
    const float* gx  = dir ? gxw : gxh;
    float* outp      = dir ? owp : ohp;

    const int tid = threadIdx.x;
    const int g  = tid >> 1;
    const int kh = tid & 1;

    // stage weights: thread loads its own 64-float half-row
    {
        const float* src = whh + g*128 + kh*64;
        float* dst = whh2 + g*136 + kh*68;
#pragma unroll
        for (int j = 0; j < 16; j++)
            *(float4*)(dst + j*4) = *(const float4*)(src + j*4);
    }

    // tail-role setup
    const int c  = tid & 127;
    const int sh = (tid >> 7) & 1;        // seq half (only meaningful tid<256)
    float hreg[4];
    float bh_r = 0.f, bh_z = 0.f, bh_n = 0.f;
    if (tid < 256) {
#pragma unroll
        for (int j = 0; j < 4; j++) hreg[j] = 0.f;
        if (tid < 128) {
#pragma unroll
            for (int s2 = 0; s2 < 8; s2++) hbuf[c*8 + s2] = 0.f;
        }
        bh_r = bhh[c];
        bh_z = bhh[c + 128];
        bh_n = bhh[c + 256];
    }
    __syncthreads();

#define PIXAT(t, s2) (dir ? ((b*64 + q0+(s2))*64 + (t)) : ((b*64 + (t))*64 + q0+(s2)))

    const float* wptr = whh2 + g*136 + kh*68;
    const int kbase = kh * 64;

    for (int t = 0; t < 64; t++) {
        // tail threads issue gx loads for this step (hidden under FMA phase)
        float gr[4], gz[4], gn[4];
        if (tid < 256) {
#pragma unroll
            for (int j = 0; j < 4; j++) {
                const float* base = gx + (size_t)PIXAT(t, sh*4 + j) * K3;
                gr[j] = base[c];
                gz[j] = base[128 + c];
                gn[j] = base[256 + c];
            }
        }

        // FMA phase: partial matvec over this thread's 64 k values
        unsigned long long a0 = 0, a1 = 0, a2 = 0, a3 = 0;
#pragma unroll
        for (int kk0 = 0; kk0 < 64; kk0 += 4) {
            float4 wv = *(const float4*)(wptr + kk0);
            const float wf[4] = {wv.x, wv.y, wv.z, wv.w};
#pragma unroll
            for (int j = 0; j < 4; j++) {
                int k = kbase + kk0 + j;
                const ulonglong2* hp = reinterpret_cast<const ulonglong2*>(hbuf + k*8);
                ulonglong2 hA = hp[0];
                ulonglong2 hB = hp[1];
                unsigned long long w2;
                PACK2(w2, wf[j]);
                FMA2(a0, hA.x, w2); FMA2(a1, hA.y, w2);
                FMA2(a2, hB.x, w2); FMA2(a3, hB.y, w2);
            }
        }
        // pair-reduce across k-halves (adjacent lanes)
        float sv[8];
        {
            float2 f;
            f = *reinterpret_cast<float2*>(&a0); sv[0] = f.x; sv[1] = f.y;
            f = *reinterpret_cast<float2*>(&a1); sv[2] = f.x; sv[3] = f.y;
            f = *reinterpret_cast<float2*>(&a2); sv[4] = f.x; sv[5] = f.y;
            f = *reinterpret_cast<float2*>(&a3); sv[6] = f.x; sv[7] = f.y;
        }
#pragma unroll
        for (int s2 = 0; s2 < 8; s2++)
            sv[s2] += __shfl_xor_sync(0xffffffffu, sv[s2], 1);
        if (kh == 0) {
#pragma unroll
            for (int s2 = 0; s2 < 8; s2++)
                sg[g*9 + s2] = sv[s2];
        }
        __syncthreads();

        // tail: nonlinearity + h update for 4 seqs per thread
        if (tid < 256) {
#pragma unroll
            for (int j = 0; j < 4; j++) {
                int s2 = sh*4 + j;
                float rp = sg[c*9 + s2]        + bh_r + gr[j];
                float zp = sg[(c+128)*9 + s2]  + bh_z + gz[j];
                float sn = sg[(c+256)*9 + s2]  + bh_n;
                float er = __expf(-rp);
                float ez = __expf(-zp);
                float r = __fdividef(1.f, 1.f + er);
                float z = __fdividef(1.f, 1.f + ez);
                float xn = gn[j] + r * sn;
                float en = __expf(2.f * xn);
                float n = 1.f - __fdividef(2.f, en + 1.f);
                float hnew = (1.f - z) * n + z * hreg[j];
                hreg[j] = hnew;
                hbuf[c*8 + s2] = hnew;
                outp[(size_t)PIXAT(t, s2) * DIMC + c] = hnew;
            }
        }
        __syncthreads();
    }
#undef PIXAT
}

// ======================================================================
// Tail: scanned = oh+ow; gate GEMM + sigmoid; gated; proj_out GEMM +
// affine/relu + residual; transposed channel-major store.
// ======================================================================
#define TAIL_SMEM ((2*64*130 + 16*132 + 128*66) * 4)

__global__ void tail_kernel(const float* __restrict__ ohp,
                            const float* __restrict__ owp,
                            const float* __restrict__ xres,
                            const float* __restrict__ gate_w,
                            const float* __restrict__ gate_b,
                            const float* __restrict__ pw,
                            const float* __restrict__ pscale,
                            const float* __restrict__ pshift,
                            float* __restrict__ out)
{
    extern __shared__ float sm[];
    float* s_full = sm;                 // [64][130]
    float* g_full = sm + 64*130;        // [64][130]
    float* w_s    = sm + 2*64*130;      // [16][132]
    float* st     = w_s + 16*132;       // [128][66]

    const int m0  = blockIdx.x * 64;
    const int b   = m0 >> 12;
    const int hw0 = m0 & 4095;
    const int tid = threadIdx.x;
    const int tx = tid & 15, ty = tid >> 4;

    for (int i = tid; i < 64*32; i += 256) {
        int mm = i >> 5, kq = i & 31;
        float4 a = *(const float4*)(ohp + (size_t)(m0+mm)*DIMC + kq*4);
        float4 c = *(const float4*)(owp + (size_t)(m0+mm)*DIMC + kq*4);
        s_full[mm*130 + kq*4 + 0] = a.x + c.x;
        s_full[mm*130 + kq*4 + 1] = a.y + c.y;
        s_full[mm*130 + kq*4 + 2] = a.z + c.z;
        s_full[mm*130 + kq*4 + 3] = a.w + c.w;
    }
    __syncthreads();

    float acc[4][8];
    #pragma unroll
    for (int i = 0; i < 4; i++)
        #pragma unroll
        for (int j = 0; j < 8; j++) acc[i][j] = 0.f;

    for (int k0 = 0; k0 < 128; k0 += 16) {
        #pragma unroll
        for (int r = 0; r < 2; r++) {
            int id2 = tid + r*256;
            int nn = id2 >> 2, kq = id2 & 3;
            float4 v = *(const float4*)(gate_w + (size_t)nn*128 + k0 + kq*4);
            w_s[(kq*4+0)*132+nn] = v.x;
            w_s[(kq*4+1)*132+nn] = v.y;
            w_s[(kq*4+2)*132+nn] = v.z;
            w_s[(kq*4+3)*132+nn] = v.w;
        }
        __syncthreads();
        #pragma unroll
        for (int kk = 0; kk < 16; kk++) {
            float av[4], bv[8];
            #pragma unroll
            for (int i = 0; i < 4; i++) av[i] = s_full[(ty+16*i)*130 + k0 + kk];
            #pragma unroll
            for (int j = 0; j < 8; j++) bv[j] = w_s[kk*132 + tx + 16*j];
            #pragma unroll
            for (int i = 0; i < 4; i++)
                #pragma unroll
                for (int j = 0; j < 8; j++)
                    acc[i][j] = fmaf(av[i], bv[j], acc[i][j]);
        }
        __syncthreads();
    }

    #pragma unroll
    for (int i = 0; i < 4; i++) {
        int mm = ty + 16*i;
        #pragma unroll
        for (int j = 0; j < 8; j++) {
            int nn = tx + 16*j;
            float e = __expf(-(acc[i][j] + gate_b[nn]));
            float gsig = __fdividef(1.f, 1.f + e);
            g_full[mm*130 + nn] = s_full[mm*130 + nn] * gsig;
        }
    }
    __syncthreads();

    float acc2[4][8];
    #pragma unroll
    for (int i = 0; i < 4; i++)
        #pragma unroll
        for (int j = 0; j < 8; j++) acc2[i][j] = 0.f;

    for (int k0 = 0; k0 < 128; k0 += 16) {
        #pragma unroll
        for (int r = 0; r < 2; r++) {
            int id2 = tid + r*256;
            int nn = id2 >> 2, kq = id2 & 3;
            float4 v = *(const float4*)(pw + (size_t)nn*128 + k0 + kq*4);
            w_s[(kq*4+0)*132+nn] = v.x;
            w_s[(kq*4+1)*132+nn] = v.y;
            w_s[(kq*4+2)*132+nn] = v.z;
            w_s[(kq*4+3)*132+nn] = v.w;
        }
        __syncthreads();
        #pragma unroll
        for (int kk = 0; kk < 16; kk++) {
            float av[4], bv[8];
            #pragma unroll
            for (int i = 0; i < 4; i++) av[i] = g_full[(ty+16*i)*130 + k0 + kk];
            #pragma unroll
            for (int j = 0; j < 8; j++) bv[j] = w_s[kk*132 + tx + 16*j];
            #pragma unroll
            for (int i = 0; i < 4; i++)
                #pragma unroll
                for (int j = 0; j < 8; j++)
                    acc2[i][j] = fmaf(av[i], bv[j], acc2[i][j]);
        }
        __syncthreads();
    }

    #pragma unroll
    for (int i = 0; i < 4; i++) {
        int mm = ty + 16*i;
        #pragma unroll
        for (int j = 0; j < 8; j++) {
            int nn = tx + 16*j;
            float v = fmaxf(fmaf(acc2[i][j], pscale[nn], pshift[nn]), 0.f)
                    + xres[(size_t)(m0+mm)*DIMC + nn];
            st[nn*66 + mm] = v;
        }
    }
    __syncthreads();

    for (int i = tid; i < 128*64; i += 256) {
        int nn = i >> 6, mm = i & 63;
        out[(size_t)(b*128 + nn)*HW + hw0 + mm] = st[nn*66 + mm];
    }
}

// ======================================================================
// Launch
// ======================================================================
extern "C" void kernel_launch(void* const* d_in, const int* in_sizes, int n_in,
                              void* d_out, int out_size)
{
    const float* l     = (const float*)d_in[0];
    const float* m_    = (const float*)d_in[1];
    const float* s_    = (const float*)d_in[2];
    const float* piw   = (const float*)d_in[3];
    const float* pisc  = (const float*)d_in[4];
    const float* pish  = (const float*)d_in[5];
    const float* wih_h = (const float*)d_in[6];
    const float* whh_h = (const float*)d_in[7];
    const float* bih_h = (const float*)d_in[8];
    const float* bhh_h = (const float*)d_in[9];
    const float* wih_w = (const float*)d_in[10];
    const float* whh_w = (const float*)d_in[11];
    const float* bih_w = (const float*)d_in[12];
    const float* bhh_w = (const float*)d_in[13];
    const float* gw    = (const float*)d_in[14];
    const float* gb    = (const float*)d_in[15];
    const float* pow_  = (const float*)d_in[16];
    const float* posc  = (const float*)d_in[17];
    const float* posh  = (const float*)d_in[18];
    float* out = (float*)d_out;

    void *p_xcat, *p_x, *p_gxh, *p_gxw, *p_oh, *p_ow;
    cudaGetSymbolAddress(&p_xcat, g_xcat);
    cudaGetSymbolAddress(&p_x,    g_x);
    cudaGetSymbolAddress(&p_gxh,  g_gxh);
    cudaGetSymbolAddress(&p_gxw,  g_gxw);
    cudaGetSymbolAddress(&p_oh,   g_oh);
    cudaGetSymbolAddress(&p_ow,   g_ow);
    float* xcat = (float*)p_xcat;
    float* x    = (float*)p_x;
    float* gxh  = (float*)p_gxh;
    float* gxw  = (float*)p_gxw;
    float* oh   = (float*)p_oh;
    float* ow   = (float*)p_ow;

    cudaFuncSetAttribute(mma_proj_kernel, cudaFuncAttributeMaxDynamicSharedMemorySize, MMA_SMEM);
    cudaFuncSetAttribute(mma_gx_kernel,   cudaFuncAttributeMaxDynamicSharedMemorySize, MMA_SMEM);
    cudaFuncSetAttribute(scan_kernel,     cudaFuncAttributeMaxDynamicSharedMemorySize, SCAN_SMEM);
    cudaFuncSetAttribute(tail_kernel,     cudaFuncAttributeMaxDynamicSharedMemorySize, TAIL_SMEM);

    // 1. resize + concat
    resize_concat_kernel<<<BATCH*HGT, 256>>>(l, m_, s_, xcat);

    // 2. proj_in (bf16x3 warp MMA)
    mma_proj_kernel<<<M_TOT/128, 256, MMA_SMEM>>>(xcat, piw, pisc, pish, x);

    // 3. gx for both directions (bf16x3 warp MMA)
    mma_gx_kernel<<<dim3(M_TOT/128, 2), 256, MMA_SMEM>>>(x, wih_h, bih_h, wih_w, bih_w, gxh, gxw);

    // 4. both GRU scans (k-split gate-split, f32x2, 24 warps/block)
    scan_kernel<<<128, 768, SCAN_SMEM>>>(whh_h, bhh_h, whh_w, bhh_w, gxh, gxw, oh, ow);

    // 5. gate + proj_out + residual + transposed store
    tail_kernel<<<M_TOT/64, 256, TAIL_SMEM>>>(oh, ow, x, gw, gb, pow_, posc, posh, out);
}

// round 7
// speedup vs baseline: 2.0653x; 2.0653x over previous
#include <cuda_runtime.h>
#include <cuda_bf16.h>
#include <math.h>
#include <stdint.h>

// ---------------- problem constants ----------------
#define BATCH 8
#define DIMC 128
#define HGT 64
#define WID 64
#define HW 4096
#define M_TOT 32768       // BATCH*HGT*WID
#define K3 384

// ---------------- scratch ----------------
__device__ float g_xcat[M_TOT * K3];
__device__ float g_x[M_TOT * DIMC];
__device__ float g_gxh[M_TOT * K3];
__device__ float g_gxw[M_TOT * K3];
__device__ float g_oh[M_TOT * DIMC];
__device__ float g_ow[M_TOT * DIMC];

// ======================================================================
// helpers
// ======================================================================
__device__ __forceinline__ uint32_t smem_u32(const void* p) {
    uint32_t a;
    asm("{ .reg .u64 t; cvta.to.shared.u64 t, %1; cvt.u32.u64 %0, t; }"
        : "=r"(a) : "l"(p));
    return a;
}

__device__ __forceinline__ void ldsm4(uint32_t* r, uint32_t addr) {
    asm volatile("ldmatrix.sync.aligned.m8n8.x4.shared.b16 {%0,%1,%2,%3}, [%4];"
                 : "=r"(r[0]), "=r"(r[1]), "=r"(r[2]), "=r"(r[3]) : "r"(addr));
}

__device__ __forceinline__ void ldsm2(uint32_t* r, uint32_t addr) {
    asm volatile("ldmatrix.sync.aligned.m8n8.x2.shared.b16 {%0,%1}, [%2];"
                 : "=r"(r[0]), "=r"(r[1]) : "r"(addr));
}

__device__ __forceinline__ void mma16816(float* c, const uint32_t* a, const uint32_t* b) {
    asm volatile(
        "mma.sync.aligned.m16n8k16.row.col.f32.bf16.bf16.f32 "
        "{%0,%1,%2,%3}, {%4,%5,%6,%7}, {%8,%9}, {%0,%1,%2,%3};"
        : "+f"(c[0]), "+f"(c[1]), "+f"(c[2]), "+f"(c[3])
        : "r"(a[0]), "r"(a[1]), "r"(a[2]), "r"(a[3]), "r"(b[0]), "r"(b[1]));
}

// convert float4 -> bf16 hi pair + bf16 lo-residual pair
__device__ __forceinline__ void cvt4(float4 v, uint2& hi, uint2& lo) {
    unsigned short b0 = __bfloat16_as_ushort(__float2bfloat16(v.x));
    unsigned short b1 = __bfloat16_as_ushort(__float2bfloat16(v.y));
    unsigned short b2 = __bfloat16_as_ushort(__float2bfloat16(v.z));
    unsigned short b3 = __bfloat16_as_ushort(__float2bfloat16(v.w));
    hi.x = ((uint32_t)b1 << 16) | (uint32_t)b0;
    hi.y = ((uint32_t)b3 << 16) | (uint32_t)b2;
    float r0 = v.x - __uint_as_float((uint32_t)b0 << 16);
    float r1 = v.y - __uint_as_float((uint32_t)b1 << 16);
    float r2 = v.z - __uint_as_float((uint32_t)b2 << 16);
    float r3 = v.w - __uint_as_float((uint32_t)b3 << 16);
    unsigned short c0 = __bfloat16_as_ushort(__float2bfloat16(r0));
    unsigned short c1 = __bfloat16_as_ushort(__float2bfloat16(r1));
    unsigned short c2 = __bfloat16_as_ushort(__float2bfloat16(r2));
    unsigned short c3 = __bfloat16_as_ushort(__float2bfloat16(r3));
    lo.x = ((uint32_t)c1 << 16) | (uint32_t)c0;
    lo.y = ((uint32_t)c3 << 16) | (uint32_t)c2;
}

// ======================================================================
// bf16x3 warp-MMA NT GEMM (coalesced staging) — unchanged (passing)
// ======================================================================
#define SA_STRIDE 136
#define MMA_SMEM (104448)

template<int KSLABS, int NTILES, int EPI>
__device__ void mma_core(const float* __restrict__ A0, int lda,
                         const float* __restrict__ B0, int ldb,
                         const float* __restrict__ p0, const float* __restrict__ p1,
                         float* __restrict__ C0, int ldc)
{
    extern __shared__ char smraw[];
    __nv_bfloat16* sa_hi = (__nv_bfloat16*)(smraw);
    __nv_bfloat16* sa_lo = (__nv_bfloat16*)(smraw + 34816);
    __nv_bfloat16* sb_hi = (__nv_bfloat16*)(smraw + 69632);
    __nv_bfloat16* sb_lo = (__nv_bfloat16*)(smraw + 87040);
    const uint32_t sbase = smem_u32(smraw);
    const uint32_t u_sa_hi = sbase;
    const uint32_t u_sa_lo = sbase + 34816;
    const uint32_t u_sb_hi = sbase + 69632;
    const uint32_t u_sb_lo = sbase + 87040;

    const int tid  = threadIdx.x;
    const int wid  = tid >> 5;
    const int lane = tid & 31;
    const int wm = wid >> 1;
    const int wn = wid & 1;
    const int gid = lane >> 2, tig = lane & 3;
    const int col4 = (tid & 31) * 4;
    const int rbase = tid >> 5;

#pragma unroll 1
    for (int nt = 0; nt < NTILES; nt++) {
        float acc[2][4][4];
#pragma unroll
        for (int i = 0; i < 2; i++)
#pragma unroll
            for (int j = 0; j < 4; j++)
#pragma unroll
                for (int e = 0; e < 4; e++) acc[i][j][e] = 0.f;

#pragma unroll 1
        for (int s = 0; s < KSLABS; s++) {
            __syncthreads();
            if (nt == 0 || KSLABS > 1) {
#pragma unroll
                for (int j = 0; j < 16; j++) {
                    int r = rbase + 8 * j;
                    float4 v = *(const float4*)(A0 + (size_t)r * lda + s * 128 + col4);
                    uint2 hi, lo; cvt4(v, hi, lo);
                    *(uint2*)(sa_hi + r * SA_STRIDE + col4) = hi;
                    *(uint2*)(sa_lo + r * SA_STRIDE + col4) = lo;
                }
            }
            {
#pragma unroll
                for (int j = 0; j < 8; j++) {
                    int r = rbase + 8 * j;
                    float4 v = *(const float4*)(B0 + (size_t)(nt * 64 + r) * ldb + s * 128 + col4);
                    uint2 hi, lo; cvt4(v, hi, lo);
                    *(uint2*)(sb_hi + r * SA_STRIDE + col4) = hi;
                    *(uint2*)(sb_lo + r * SA_STRIDE + col4) = lo;
                }
            }
            __syncthreads();

#pragma unroll
            for (int ch = 0; ch < 8; ch++) {
                const int k = ch * 16;
                uint32_t ah[2][4], al[2][4];
#pragma unroll
                for (int i = 0; i < 2; i++) {
                    uint32_t off = (uint32_t)(((wm*32 + i*16 + (lane & 15)) * SA_STRIDE
                                               + k + ((lane >> 4) << 3)) * 2);
                    ldsm4(ah[i], u_sa_hi + off);
                    ldsm4(al[i], u_sa_lo + off);
                }
                uint32_t bh[4][2], bl[4][2];
#pragma unroll
                for (int nb = 0; nb < 2; nb++) {
                    int row = wn*32 + nb*16 + (lane & 7) + ((lane >> 4) << 3);
                    int col = k + ((lane >> 3) & 1) * 8;
                    uint32_t off = (uint32_t)((row * SA_STRIDE + col) * 2);
                    uint32_t r[4];
                    ldsm4(r, u_sb_hi + off);
                    bh[2*nb][0] = r[0]; bh[2*nb][1] = r[1];
                    bh[2*nb+1][0] = r[2]; bh[2*nb+1][1] = r[3];
                    ldsm4(r, u_sb_lo + off);
                    bl[2*nb][0] = r[0]; bl[2*nb][1] = r[1];
                    bl[2*nb+1][0] = r[2]; bl[2*nb+1][1] = r[3];
                }
#pragma unroll
                for (int i = 0; i < 2; i++)
#pragma unroll
                    for (int j = 0; j < 4; j++) {
                        mma16816(acc[i][j], ah[i], bh[j]);
                        mma16816(acc[i][j], ah[i], bl[j]);
                        mma16816(acc[i][j], al[i], bh[j]);
                    }
            }
        }

#pragma unroll
        for (int i = 0; i < 2; i++) {
            int mrow = wm*32 + i*16 + gid;
#pragma unroll
            for (int j = 0; j < 4; j++) {
                int ncol = nt*64 + wn*32 + j*8 + tig*2;
                float2 q0 = *(const float2*)(p0 + ncol);
                float2 q1 = (EPI == 0) ? *(const float2*)(p1 + ncol)
                                       : make_float2(0.f, 0.f);
                float v0, v1, v2, v3;
                if (EPI == 0) {
                    v0 = fmaxf(fmaf(acc[i][j][0], q0.x, q1.x), 0.f);
                    v1 = fmaxf(fmaf(acc[i][j][1], q0.y, q1.y), 0.f);
                    v2 = fmaxf(fmaf(acc[i][j][2], q0.x, q1.x), 0.f);
                    v3 = fmaxf(fmaf(acc[i][j][3], q0.y, q1.y), 0.f);
                } else {
                    v0 = acc[i][j][0] + q0.x;
                    v1 = acc[i][j][1] + q0.y;
                    v2 = acc[i][j][2] + q0.x;
                    v3 = acc[i][j][3] + q0.y;
                }
                *(float2*)(C0 + (size_t)mrow * ldc + ncol) = make_float2(v0, v1);
                *(float2*)(C0 + (size_t)(mrow + 8) * ldc + ncol) = make_float2(v2, v3);
            }
        }
    }
}

__global__ void __launch_bounds__(256)
mma_proj_kernel(const float* __restrict__ xcat, const float* __restrict__ piw,
                const float* __restrict__ pisc, const float* __restrict__ pish,
                float* __restrict__ x)
{
    mma_core<3, 2, 0>(xcat + (size_t)blockIdx.x * 128 * K3, K3,
                      piw, K3, pisc, pish,
                      x + (size_t)blockIdx.x * 128 * DIMC, DIMC);
}

__global__ void __launch_bounds__(256)
mma_gx_kernel(const float* __restrict__ x,
              const float* __restrict__ wih_h, const float* __restrict__ bih_h,
              const float* __restrict__ wih_w, const float* __restrict__ bih_w,
              float* __restrict__ gxh, float* __restrict__ gxw)
{
    const float* B    = blockIdx.y ? wih_w : wih_h;
    const float* bias = blockIdx.y ? bih_w : bih_h;
    float* out        = blockIdx.y ? gxw : gxh;
    mma_core<1, 6, 1>(x + (size_t)blockIdx.x * 128 * DIMC, DIMC,
                      B, DIMC, bias, nullptr,
                      out + (size_t)blockIdx.x * 128 * K3, K3);
}

// ======================================================================
// resize + concat (unchanged, passing)
// ======================================================================
__global__ void __launch_bounds__(256)
resize_concat_kernel(const float* __restrict__ l,
                     const float* __restrict__ mid,
                     const float* __restrict__ s,
                     float* __restrict__ xcat)
{
    __shared__ float st[64 * 65];
    const int bh = blockIdx.x;
    const int b = bh >> 6, h = bh & 63;
    const int tid = threadIdx.x;
    const int wq = tid & 63;
    const int cl = tid >> 6;

    int ljh[4]; float lwh[4];
    int ljw[4]; float lww[4];
    {
        float sum = 0.f;
#pragma unroll
        for (int t = 0; t < 4; t++) {
            int jj = 2*h - 1 + t;
            float r = (t == 0 || t == 3) ? 0.25f : 0.75f;
            bool ok = (jj >= 0 && jj < 128);
            ljh[t] = ok ? jj : 0;
            lwh[t] = ok ? r : 0.f;
            sum += lwh[t];
        }
        float inv = 1.f / sum;
#pragma unroll
        for (int t = 0; t < 4; t++) lwh[t] *= inv;
    }
    {
        float sum = 0.f;
#pragma unroll
        for (int t = 0; t < 4; t++) {
            int jj = 2*wq - 1 + t;
            float r = (t == 0 || t == 3) ? 0.25f : 0.75f;
            bool ok = (jj >= 0 && jj < 128);
            ljw[t] = ok ? jj : 0;
            lww[t] = ok ? r : 0.f;
            sum += lww[t];
        }
        float inv = 1.f / sum;
#pragma unroll
        for (int t = 0; t < 4; t++) lww[t] *= inv;
    }
    int sjh[2]; float swh[2];
    int sjw[2]; float sww[2];
    {
        float p = 0.5f*h - 0.25f;
        int j0 = (int)floorf(p);
        float f = p - (float)j0;
        bool o0 = (j0 >= 0 && j0 < 32), o1 = (j0+1 >= 0 && j0+1 < 32);
        swh[0] = o0 ? (1.f - f) : 0.f; sjh[0] = o0 ? j0 : 0;
        swh[1] = o1 ? f : 0.f;         sjh[1] = o1 ? (j0+1) : 0;
        float inv = 1.f / (swh[0] + swh[1]);
        swh[0] *= inv; swh[1] *= inv;
    }
    {
        float p = 0.5f*wq - 0.25f;
        int j0 = (int)floorf(p);
        float f = p - (float)j0;
        bool o0 = (j0 >= 0 && j0 < 32), o1 = (j0+1 >= 0 && j0+1 < 32);
        sww[0] = o0 ? (1.f - f) : 0.f; sjw[0] = o0 ? j0 : 0;
        sww[1] = o1 ? f : 0.f;         sjw[1] = o1 ? (j0+1) : 0;
        float inv = 1.f / (sww[0] + sww[1]);
        sww[0] *= inv; sww[1] *= inv;
    }

    const int ww = tid >> 2;
    const int c0 = (tid & 3) * 16;

#pragma unroll 1
    for (int chunk = 0; chunk < 6; chunk++) {
        const int cbase = chunk * 64;
        if (chunk < 2) {
#pragma unroll 4
            for (int i = 0; i < 16; i++) {
                int c = cbase + cl + 4*i;
                const float* lp = l + ((size_t)(b*128 + c) << 14);
                float v = 0.f;
#pragma unroll
                for (int a = 0; a < 4; a++) {
                    const float* row = lp + (ljh[a] << 7);
                    float ra = lww[0]*row[ljw[0]] + lww[1]*row[ljw[1]]
                             + lww[2]*row[ljw[2]] + lww[3]*row[ljw[3]];
                    v = fmaf(lwh[a], ra, v);
                }
                st[(cl + 4*i) * 65 + wq] = v;
            }
        } else if (chunk < 4) {
#pragma unroll 4
            for (int i = 0; i < 16; i++) {
                int c = cbase - 128 + cl + 4*i;
                st[(cl + 4*i) * 65 + wq] =
                    mid[((size_t)(b*128 + c) << 12) + (h << 6) + wq];
            }
        } else {
#pragma unroll 4
            for (int i = 0; i < 16; i++) {
                int c = cbase - 256 + cl + 4*i;
                const float* sp = s + ((size_t)(b*128 + c) << 10);
                const float* r0 = sp + (sjh[0] << 5);
                const float* r1 = sp + (sjh[1] << 5);
                float v = swh[0]*(sww[0]*r0[sjw[0]] + sww[1]*r0[sjw[1]])
                        + swh[1]*(sww[0]*r1[sjw[0]] + sww[1]*r1[sjw[1]]);
                st[(cl + 4*i) * 65 + wq] = v;
            }
        }
        __syncthreads();
        float* dst = xcat + (size_t)(bh*64 + ww) * K3 + cbase + c0;
#pragma unroll
        for (int j = 0; j < 4; j++) {
            int cc = c0 + 4*j;
            float4 v = make_float4(st[(cc+0)*65 + ww], st[(cc+1)*65 + ww],
                                   st[(cc+2)*65 + ww], st[(cc+3)*65 + ww]);
            *(float4*)(dst + 4*j) = v;
        }
        __syncthreads();
    }
}

// ======================================================================
// Scan kernel v3: tensor-core GRU. 128 blocks x 384 threads (12 warps).
// Per step: D[384,8] = W[384,128] @ h[128,8] via mma.sync m16n8k16,
// bf16x3 error compensation (W hi/lo staged once; h hi/lo refreshed per step).
// Warp w owns gates [w*32, w*32+32) = 2 m16 tiles; N=8 = one n-tile.
// Tail (tid<256): 4 seqs/thread, gx prefetch, nonlinearity, h update.
// ======================================================================
#define W_OFF_LO 104448
#define H_OFF_HI 208896
#define H_OFF_LO 211072
#define SG_OFF   213248
#define SCAN_SMEM (SG_OFF + 384*9*4)   // 227,072 bytes

__global__ void __launch_bounds__(384, 1)
scan_kernel(const float* __restrict__ whh_h,
            const float* __restrict__ bhh_h,
            const float* __restrict__ whh_w,
            const float* __restrict__ bhh_w,
            const float* __restrict__ gxh,
            const float* __restrict__ gxw,
            float* __restrict__ ohp,
            float* __restrict__ owp)
{
    extern __shared__ char smraw[];
    __nv_bfloat16* w_hi = (__nv_bfloat16*)(smraw);              // [384][136]
    __nv_bfloat16* w_lo = (__nv_bfloat16*)(smraw + W_OFF_LO);   // [384][136]
    __nv_bfloat16* h_hi = (__nv_bfloat16*)(smraw + H_OFF_HI);   // [8][136]
    __nv_bfloat16* h_lo = (__nv_bfloat16*)(smraw + H_OFF_LO);   // [8][136]
    float* sg = (float*)(smraw + SG_OFF);                       // [384][9]

    const uint32_t sbase = smem_u32(smraw);
    const uint32_t u_w_hi = sbase;
    const uint32_t u_w_lo = sbase + W_OFF_LO;
    const uint32_t u_h_hi = sbase + H_OFF_HI;
    const uint32_t u_h_lo = sbase + H_OFF_LO;

    const int dir = blockIdx.x >> 6;
    const int sub = blockIdx.x & 63;
    const int b   = sub >> 3;
    const int q0  = (sub & 7) << 3;

    const float* whh = dir ? whh_w : whh_h;
    const float* bhh = dir ? bhh_w : bhh_h;
    const float* gx  = dir ? gxw : gxh;
    float* outp      = dir ? owp : ohp;

    const int tid  = threadIdx.x;
    const int lane = tid & 31;
    const int wrp  = tid >> 5;          // 0..11, gate base = wrp*32

    // ---- stage W hi/lo (coalesced) ----
    {
        const int col4 = lane * 4;
#pragma unroll
        for (int j = 0; j < 32; j++) {
            int r = wrp * 32 + j;
            float4 v = *(const float4*)(whh + (size_t)r * 128 + col4);
            uint2 hi, lo; cvt4(v, hi, lo);
            *(uint2*)(w_hi + r * SA_STRIDE + col4) = hi;
            *(uint2*)(w_lo + r * SA_STRIDE + col4) = lo;
        }
    }
    // ---- zero h bufs (incl. padding) ----
    for (int i = tid; i < 8 * SA_STRIDE; i += 384) {
        h_hi[i] = __ushort_as_bfloat16((unsigned short)0);
        h_lo[i] = __ushort_as_bfloat16((unsigned short)0);
    }

    // ---- tail-role setup ----
    const int c  = tid & 127;
    const int sh = (tid >> 7) & 1;
    float hreg[4];
    float bh_r = 0.f, bh_z = 0.f, bh_n = 0.f;
    if (tid < 256) {
#pragma unroll
        for (int j = 0; j < 4; j++) hreg[j] = 0.f;
        bh_r = bhh[c];
        bh_z = bhh[c + 128];
        bh_n = bhh[c + 256];
    }
    __syncthreads();

#define PIXAT(t, s2) (dir ? ((b*64 + q0+(s2))*64 + (t)) : ((b*64 + (t))*64 + q0+(s2)))

    // fragment address pieces (loop-invariant)
    const uint32_t a_off0 = (uint32_t)(((wrp*32 + (lane & 15)) * SA_STRIDE
                                        + ((lane >> 4) << 3)) * 2);
    const uint32_t b_off  = (uint32_t)((((lane & 7) * SA_STRIDE)
                                        + (((lane >> 3) & 1) << 3)) * 2);
    const int grow = wrp*32 + (lane >> 2);
    const int scol = (lane & 3) * 2;

    for (int t = 0; t < 64; t++) {
        // gx prefetch (consumed in tail phase; hidden under mma phase)
        float gr[4], gz[4], gn[4];
        if (tid < 256) {
#pragma unroll
            for (int j = 0; j < 4; j++) {
                const float* base = gx + (size_t)PIXAT(t, sh*4 + j) * K3;
                gr[j] = base[c];
                gz[j] = base[128 + c];
                gn[j] = base[256 + c];
            }
        }

        // ---- mma phase: D = Whi*hhi + Whi*hlo + Wlo*hhi ----
        float acc[2][4];
#pragma unroll
        for (int i = 0; i < 2; i++)
#pragma unroll
            for (int e = 0; e < 4; e++) acc[i][e] = 0.f;

#pragma unroll
        for (int ch = 0; ch < 8; ch++) {
            const uint32_t kb = (uint32_t)(ch * 32);   // ch*16 cols * 2 bytes
            uint32_t bh2[2], bl2[2];
            ldsm2(bh2, u_h_hi + b_off + kb);
            ldsm2(bl2, u_h_lo + b_off + kb);
#pragma unroll
            for (int i = 0; i < 2; i++) {
                uint32_t ah[4], al[4];
                uint32_t aoff = a_off0 + (uint32_t)(i * 16 * SA_STRIDE * 2) + kb;
                ldsm4(ah, u_w_hi + aoff);
                ldsm4(al, u_w_lo + aoff);
                mma16816(acc[i], ah, bh2);
                mma16816(acc[i], ah, bl2);
                mma16816(acc[i], al, bh2);
            }
        }

        // store gate pre-sums to sg
#pragma unroll
        for (int i = 0; i < 2; i++) {
            int g = grow + i*16;
            sg[g*9 + scol]       = acc[i][0];
            sg[g*9 + scol + 1]   = acc[i][1];
            sg[(g+8)*9 + scol]     = acc[i][2];
            sg[(g+8)*9 + scol + 1] = acc[i][3];
        }
        __syncthreads();

        // ---- tail: nonlinearity + h update (4 seqs/thread) ----
        if (tid < 256) {
#pragma unroll
            for (int j = 0; j < 4; j++) {
                int s2 = sh*4 + j;
                float rp = sg[c*9 + s2]       + bh_r + gr[j];
                float zp = sg[(c+128)*9 + s2] + bh_z + gz[j];
                float sn = sg[(c+256)*9 + s2] + bh_n;
                float er = __expf(-rp);
                float ez = __expf(-zp);
                float r = __fdividef(1.f, 1.f + er);
                float z = __fdividef(1.f, 1.f + ez);
                float xn = gn[j] + r * sn;
                float en = __expf(2.f * xn);
                float n = 1.f - __fdividef(2.f, en + 1.f);
                float hnew = (1.f - z) * n + z * hreg[j];
                hreg[j] = hnew;
                // split h -> bf16 hi + lo residual
                unsigned short hb = __bfloat16_as_ushort(__float2bfloat16(hnew));
                float lr = hnew - __uint_as_float((uint32_t)hb << 16);
                unsigned short lb = __bfloat16_as_ushort(__float2bfloat16(lr));
                h_hi[s2 * SA_STRIDE + c] = __ushort_as_bfloat16(hb);
                h_lo[s2 * SA_STRIDE + c] = __ushort_as_bfloat16(lb);
                outp[(size_t)PIXAT(t, s2) * DIMC + c] = hnew;
            }
        }
        __syncthreads();
    }
#undef PIXAT
}

// ======================================================================
// Tail: scanned = oh+ow; gate GEMM + sigmoid; gated; proj_out GEMM +
// affine/relu + residual; transposed channel-major store. (unchanged)
// ======================================================================
#define TAIL_SMEM ((2*64*130 + 16*132 + 128*66) * 4)

__global__ void tail_kernel(const float* __restrict__ ohp,
                            const float* __restrict__ owp,
                            const float* __restrict__ xres,
                            const float* __restrict__ gate_w,
                            const float* __restrict__ gate_b,
                            const float* __restrict__ pw,
                            const float* __restrict__ pscale,
                            const float* __restrict__ pshift,
                            float* __restrict__ out)
{
    extern __shared__ float sm[];
    float* s_full = sm;
    float* g_full = sm + 64*130;
    float* w_s    = sm + 2*64*130;
    float* st     = w_s + 16*132;

    const int m0  = blockIdx.x * 64;
    const int b   = m0 >> 12;
    const int hw0 = m0 & 4095;
    const int tid = threadIdx.x;
    const int tx = tid & 15, ty = tid >> 4;

    for (int i = tid; i < 64*32; i += 256) {
        int mm = i >> 5, kq = i & 31;
        float4 a = *(const float4*)(ohp + (size_t)(m0+mm)*DIMC + kq*4);
        float4 c = *(const float4*)(owp + (size_t)(m0+mm)*DIMC + kq*4);
        s_full[mm*130 + kq*4 + 0] = a.x + c.x;
        s_full[mm*130 + kq*4 + 1] = a.y + c.y;
        s_full[mm*130 + kq*4 + 2] = a.z + c.z;
        s_full[mm*130 + kq*4 + 3] = a.w + c.w;
    }
    __syncthreads();

    float acc[4][8];
    #pragma unroll
    for (int i = 0; i < 4; i++)
        #pragma unroll
        for (int j = 0; j < 8; j++) acc[i][j] = 0.f;

    for (int k0 = 0; k0 < 128; k0 += 16) {
        #pragma unroll
        for (int r = 0; r < 2; r++) {
            int id2 = tid + r*256;
            int nn = id2 >> 2, kq = id2 & 3;
            float4 v = *(const float4*)(gate_w + (size_t)nn*128 + k0 + kq*4);
            w_s[(kq*4+0)*132+nn] = v.x;
            w_s[(kq*4+1)*132+nn] = v.y;
            w_s[(kq*4+2)*132+nn] = v.z;
            w_s[(kq*4+3)*132+nn] = v.w;
        }
        __syncthreads();
        #pragma unroll
        for (int kk = 0; kk < 16; kk++) {
            float av[4], bv[8];
            #pragma unroll
            for (int i = 0; i < 4; i++) av[i] = s_full[(ty+16*i)*130 + k0 + kk];
            #pragma unroll
            for (int j = 0; j < 8; j++) bv[j] = w_s[kk*132 + tx + 16*j];
            #pragma unroll
            for (int i = 0; i < 4; i++)
                #pragma unroll
                for (int j = 0; j < 8; j++)
                    acc[i][j] = fmaf(av[i], bv[j], acc[i][j]);
        }
        __syncthreads();
    }

    #pragma unroll
    for (int i = 0; i < 4; i++) {
        int mm = ty + 16*i;
        #pragma unroll
        for (int j = 0; j < 8; j++) {
            int nn = tx + 16*j;
            float e = __expf(-(acc[i][j] + gate_b[nn]));
            float gsig = __fdividef(1.f, 1.f + e);
            g_full[mm*130 + nn] = s_full[mm*130 + nn] * gsig;
        }
    }
    __syncthreads();

    float acc2[4][8];
    #pragma unroll
    for (int i = 0; i < 4; i++)
        #pragma unroll
        for (int j = 0; j < 8; j++) acc2[i][j] = 0.f;

    for (int k0 = 0; k0 < 128; k0 += 16) {
        #pragma unroll
        for (int r = 0; r < 2; r++) {
            int id2 = tid + r*256;
            int nn = id2 >> 2, kq = id2 & 3;
            float4 v = *(const float4*)(pw + (size_t)nn*128 + k0 + kq*4);
            w_s[(kq*4+0)*132+nn] = v.x;
            w_s[(kq*4+1)*132+nn] = v.y;
            w_s[(kq*4+2)*132+nn] = v.z;
            w_s[(kq*4+3)*132+nn] = v.w;
        }
        __syncthreads();
        #pragma unroll
        for (int kk = 0; kk < 16; kk++) {
            float av[4], bv[8];
            #pragma unroll
            for (int i = 0; i < 4; i++) av[i] = g_full[(ty+16*i)*130 + k0 + kk];
            #pragma unroll
            for (int j = 0; j < 8; j++) bv[j] = w_s[kk*132 + tx + 16*j];
            #pragma unroll
            for (int i = 0; i < 4; i++)
                #pragma unroll
                for (int j = 0; j < 8; j++)
                    acc2[i][j] = fmaf(av[i], bv[j], acc2[i][j]);
        }
        __syncthreads();
    }

    #pragma unroll
    for (int i = 0; i < 4; i++) {
        int mm = ty + 16*i;
        #pragma unroll
        for (int j = 0; j < 8; j++) {
            int nn = tx + 16*j;
            float v = fmaxf(fmaf(acc2[i][j], pscale[nn], pshift[nn]), 0.f)
                    + xres[(size_t)(m0+mm)*DIMC + nn];
            st[nn*66 + mm] = v;
        }
    }
    __syncthreads();

    for (int i = tid; i < 128*64; i += 256) {
        int nn = i >> 6, mm = i & 63;
        out[(size_t)(b*128 + nn)*HW + hw0 + mm] = st[nn*66 + mm];
    }
}

// ======================================================================
// Launch
// ======================================================================
extern "C" void kernel_launch(void* const* d_in, const int* in_sizes, int n_in,
                              void* d_out, int out_size)
{
    const float* l     = (const float*)d_in[0];
    const float* m_    = (const float*)d_in[1];
    const float* s_    = (const float*)d_in[2];
    const float* piw   = (const float*)d_in[3];
    const float* pisc  = (const float*)d_in[4];
    const float* pish  = (const float*)d_in[5];
    const float* wih_h = (const float*)d_in[6];
    const float* whh_h = (const float*)d_in[7];
    const float* bih_h = (const float*)d_in[8];
    const float* bhh_h = (const float*)d_in[9];
    const float* wih_w = (const float*)d_in[10];
    const float* whh_w = (const float*)d_in[11];
    const float* bih_w = (const float*)d_in[12];
    const float* bhh_w = (const float*)d_in[13];
    const float* gw    = (const float*)d_in[14];
    const float* gb    = (const float*)d_in[15];
    const float* pow_  = (const float*)d_in[16];
    const float* posc  = (const float*)d_in[17];
    const float* posh  = (const float*)d_in[18];
    float* out = (float*)d_out;

    void *p_xcat, *p_x, *p_gxh, *p_gxw, *p_oh, *p_ow;
    cudaGetSymbolAddress(&p_xcat, g_xcat);
    cudaGetSymbolAddress(&p_x,    g_x);
    cudaGetSymbolAddress(&p_gxh,  g_gxh);
    cudaGetSymbolAddress(&p_gxw,  g_gxw);
    cudaGetSymbolAddress(&p_oh,   g_oh);
    cudaGetSymbolAddress(&p_ow,   g_ow);
    float* xcat = (float*)p_xcat;
    float* x    = (float*)p_x;
    float* gxh  = (float*)p_gxh;
    float* gxw  = (float*)p_gxw;
    float* oh   = (float*)p_oh;
    float* ow   = (float*)p_ow;

    cudaFuncSetAttribute(mma_proj_kernel, cudaFuncAttributeMaxDynamicSharedMemorySize, MMA_SMEM);
    cudaFuncSetAttribute(mma_gx_kernel,   cudaFuncAttributeMaxDynamicSharedMemorySize, MMA_SMEM);
    cudaFuncSetAttribute(scan_kernel,     cudaFuncAttributeMaxDynamicSharedMemorySize, SCAN_SMEM);
    cudaFuncSetAttribute(tail_kernel,     cudaFuncAttributeMaxDynamicSharedMemorySize, TAIL_SMEM);

    // 1. resize + concat
    resize_concat_kernel<<<BATCH*HGT, 256>>>(l, m_, s_, xcat);

    // 2. proj_in (bf16x3 warp MMA)
    mma_proj_kernel<<<M_TOT/128, 256, MMA_SMEM>>>(xcat, piw, pisc, pish, x);

    // 3. gx for both directions (bf16x3 warp MMA)
    mma_gx_kernel<<<dim3(M_TOT/128, 2), 256, MMA_SMEM>>>(x, wih_h, bih_h, wih_w, bih_w, gxh, gxw);

    // 4. both GRU scans (tensor-core recurrent matvec, bf16x3)
    scan_kernel<<<128, 384, SCAN_SMEM>>>(whh_h, bhh_h, whh_w, bhh_w, gxh, gxw, oh, ow);

    // 5. gate + proj_out + residual + transposed store
    tail_kernel<<<M_TOT/64, 256, TAIL_SMEM>>>(oh, ow, x, gw, gb, pow_, posc, posh, out);
}

// round 9
// speedup vs baseline: 2.3193x; 1.1230x over previous
#include <cuda_runtime.h>
#include <cuda_bf16.h>
#include <math.h>
#include <stdint.h>

// ---------------- problem constants ----------------
#define BATCH 8
#define DIMC 128
#define HGT 64
#define WID 64
#define HW 4096
#define M_TOT 32768       // BATCH*HGT*WID
#define K3 384

// ---------------- scratch ----------------
__device__ float g_xcat[M_TOT * K3];
__device__ float g_x[M_TOT * DIMC];
__device__ float g_gxh[M_TOT * K3];
__device__ float g_gxw[M_TOT * K3];
__device__ float g_oh[M_TOT * DIMC];
__device__ float g_ow[M_TOT * DIMC];

// ======================================================================
// helpers
// ======================================================================
__device__ __forceinline__ uint32_t smem_u32(const void* p) {
    uint32_t a;
    asm("{ .reg .u64 t; cvta.to.shared.u64 t, %1; cvt.u32.u64 %0, t; }"
        : "=r"(a) : "l"(p));
    return a;
}

__device__ __forceinline__ void ldsm4(uint32_t* r, uint32_t addr) {
    asm volatile("ldmatrix.sync.aligned.m8n8.x4.shared.b16 {%0,%1,%2,%3}, [%4];"
                 : "=r"(r[0]), "=r"(r[1]), "=r"(r[2]), "=r"(r[3]) : "r"(addr));
}

__device__ __forceinline__ void ldsm2(uint32_t* r, uint32_t addr) {
    asm volatile("ldmatrix.sync.aligned.m8n8.x2.shared.b16 {%0,%1}, [%2];"
                 : "=r"(r[0]), "=r"(r[1]) : "r"(addr));
}

__device__ __forceinline__ void mma16816(float* c, const uint32_t* a, const uint32_t* b) {
    asm volatile(
        "mma.sync.aligned.m16n8k16.row.col.f32.bf16.bf16.f32 "
        "{%0,%1,%2,%3}, {%4,%5,%6,%7}, {%8,%9}, {%0,%1,%2,%3};"
        : "+f"(c[0]), "+f"(c[1]), "+f"(c[2]), "+f"(c[3])
        : "r"(a[0]), "r"(a[1]), "r"(a[2]), "r"(a[3]), "r"(b[0]), "r"(b[1]));
}

// convert float4 -> bf16 hi pair + bf16 lo-residual pair
__device__ __forceinline__ void cvt4(float4 v, uint2& hi, uint2& lo) {
    unsigned short b0 = __bfloat16_as_ushort(__float2bfloat16(v.x));
    unsigned short b1 = __bfloat16_as_ushort(__float2bfloat16(v.y));
    unsigned short b2 = __bfloat16_as_ushort(__float2bfloat16(v.z));
    unsigned short b3 = __bfloat16_as_ushort(__float2bfloat16(v.w));
    hi.x = ((uint32_t)b1 << 16) | (uint32_t)b0;
    hi.y = ((uint32_t)b3 << 16) | (uint32_t)b2;
    float r0 = v.x - __uint_as_float((uint32_t)b0 << 16);
    float r1 = v.y - __uint_as_float((uint32_t)b1 << 16);
    float r2 = v.z - __uint_as_float((uint32_t)b2 << 16);
    float r3 = v.w - __uint_as_float((uint32_t)b3 << 16);
    unsigned short c0 = __bfloat16_as_ushort(__float2bfloat16(r0));
    unsigned short c1 = __bfloat16_as_ushort(__float2bfloat16(r1));
    unsigned short c2 = __bfloat16_as_ushort(__float2bfloat16(r2));
    unsigned short c3 = __bfloat16_as_ushort(__float2bfloat16(r3));
    lo.x = ((uint32_t)c1 << 16) | (uint32_t)c0;
    lo.y = ((uint32_t)c3 << 16) | (uint32_t)c2;
}

// ======================================================================
// bf16x3 warp-MMA NT GEMM (unchanged, passing)
// ======================================================================
#define SA_STRIDE 136
#define MMA_SMEM (104448)

template<int KSLABS, int NTILES, int EPI>
__device__ void mma_core(const float* __restrict__ A0, int lda,
                         const float* __restrict__ B0, int ldb,
                         const float* __restrict__ p0, const float* __restrict__ p1,
                         float* __restrict__ C0, int ldc)
{
    extern __shared__ char smraw[];
    __nv_bfloat16* sa_hi = (__nv_bfloat16*)(smraw);
    __nv_bfloat16* sa_lo = (__nv_bfloat16*)(smraw + 34816);
    __nv_bfloat16* sb_hi = (__nv_bfloat16*)(smraw + 69632);
    __nv_bfloat16* sb_lo = (__nv_bfloat16*)(smraw + 87040);
    const uint32_t sbase = smem_u32(smraw);
    const uint32_t u_sa_hi = sbase;
    const uint32_t u_sa_lo = sbase + 34816;
    const uint32_t u_sb_hi = sbase + 69632;
    const uint32_t u_sb_lo = sbase + 87040;

    const int tid  = threadIdx.x;
    const int wid  = tid >> 5;
    const int lane = tid & 31;
    const int wm = wid >> 1;
    const int wn = wid & 1;
    const int gid = lane >> 2, tig = lane & 3;
    const int col4 = (tid & 31) * 4;
    const int rbase = tid >> 5;

#pragma unroll 1
    for (int nt = 0; nt < NTILES; nt++) {
        float acc[2][4][4];
#pragma unroll
        for (int i = 0; i < 2; i++)
#pragma unroll
            for (int j = 0; j < 4; j++)
#pragma unroll
                for (int e = 0; e < 4; e++) acc[i][j][e] = 0.f;

#pragma unroll 1
        for (int s = 0; s < KSLABS; s++) {
            __syncthreads();
            if (nt == 0 || KSLABS > 1) {
#pragma unroll
                for (int j = 0; j < 16; j++) {
                    int r = rbase + 8 * j;
                    float4 v = *(const float4*)(A0 + (size_t)r * lda + s * 128 + col4);
                    uint2 hi, lo; cvt4(v, hi, lo);
                    *(uint2*)(sa_hi + r * SA_STRIDE + col4) = hi;
                    *(uint2*)(sa_lo + r * SA_STRIDE + col4) = lo;
                }
            }
            {
#pragma unroll
                for (int j = 0; j < 8; j++) {
                    int r = rbase + 8 * j;
                    float4 v = *(const float4*)(B0 + (size_t)(nt * 64 + r) * ldb + s * 128 + col4);
                    uint2 hi, lo; cvt4(v, hi, lo);
                    *(uint2*)(sb_hi + r * SA_STRIDE + col4) = hi;
                    *(uint2*)(sb_lo + r * SA_STRIDE + col4) = lo;
                }
            }
            __syncthreads();

#pragma unroll
            for (int ch = 0; ch < 8; ch++) {
                const int k = ch * 16;
                uint32_t ah[2][4], al[2][4];
#pragma unroll
                for (int i = 0; i < 2; i++) {
                    uint32_t off = (uint32_t)(((wm*32 + i*16 + (lane & 15)) * SA_STRIDE
                                               + k + ((lane >> 4) << 3)) * 2);
                    ldsm4(ah[i], u_sa_hi + off);
                    ldsm4(al[i], u_sa_lo + off);
                }
                uint32_t bh[4][2], bl[4][2];
#pragma unroll
                for (int nb = 0; nb < 2; nb++) {
                    int row = wn*32 + nb*16 + (lane & 7) + ((lane >> 4) << 3);
                    int col = k + ((lane >> 3) & 1) * 8;
                    uint32_t off = (uint32_t)((row * SA_STRIDE + col) * 2);
                    uint32_t r[4];
                    ldsm4(r, u_sb_hi + off);
                    bh[2*nb][0] = r[0]; bh[2*nb][1] = r[1];
                    bh[2*nb+1][0] = r[2]; bh[2*nb+1][1] = r[3];
                    ldsm4(r, u_sb_lo + off);
                    bl[2*nb][0] = r[0]; bl[2*nb][1] = r[1];
                    bl[2*nb+1][0] = r[2]; bl[2*nb+1][1] = r[3];
                }
#pragma unroll
                for (int i = 0; i < 2; i++)
#pragma unroll
                    for (int j = 0; j < 4; j++) {
                        mma16816(acc[i][j], ah[i], bh[j]);
                        mma16816(acc[i][j], ah[i], bl[j]);
                        mma16816(acc[i][j], al[i], bh[j]);
                    }
            }
        }

#pragma unroll
        for (int i = 0; i < 2; i++) {
            int mrow = wm*32 + i*16 + gid;
#pragma unroll
            for (int j = 0; j < 4; j++) {
                int ncol = nt*64 + wn*32 + j*8 + tig*2;
                float2 q0 = *(const float2*)(p0 + ncol);
                float2 q1 = (EPI == 0) ? *(const float2*)(p1 + ncol)
                                       : make_float2(0.f, 0.f);
                float v0, v1, v2, v3;
                if (EPI == 0) {
                    v0 = fmaxf(fmaf(acc[i][j][0], q0.x, q1.x), 0.f);
                    v1 = fmaxf(fmaf(acc[i][j][1], q0.y, q1.y), 0.f);
                    v2 = fmaxf(fmaf(acc[i][j][2], q0.x, q1.x), 0.f);
                    v3 = fmaxf(fmaf(acc[i][j][3], q0.y, q1.y), 0.f);
                } else {
                    v0 = acc[i][j][0] + q0.x;
                    v1 = acc[i][j][1] + q0.y;
                    v2 = acc[i][j][2] + q0.x;
                    v3 = acc[i][j][3] + q0.y;
                }
                *(float2*)(C0 + (size_t)mrow * ldc + ncol) = make_float2(v0, v1);
                *(float2*)(C0 + (size_t)(mrow + 8) * ldc + ncol) = make_float2(v2, v3);
            }
        }
    }
}

__global__ void __launch_bounds__(256)
mma_proj_kernel(const float* __restrict__ xcat, const float* __restrict__ piw,
                const float* __restrict__ pisc, const float* __restrict__ pish,
                float* __restrict__ x)
{
    mma_core<3, 2, 0>(xcat + (size_t)blockIdx.x * 128 * K3, K3,
                      piw, K3, pisc, pish,
                      x + (size_t)blockIdx.x * 128 * DIMC, DIMC);
}

__global__ void __launch_bounds__(256)
mma_gx_kernel(const float* __restrict__ x,
              const float* __restrict__ wih_h, const float* __restrict__ bih_h,
              const float* __restrict__ wih_w, const float* __restrict__ bih_w,
              float* __restrict__ gxh, float* __restrict__ gxw)
{
    const float* B    = blockIdx.y ? wih_w : wih_h;
    const float* bias = blockIdx.y ? bih_w : bih_h;
    float* out        = blockIdx.y ? gxw : gxh;
    mma_core<1, 6, 1>(x + (size_t)blockIdx.x * 128 * DIMC, DIMC,
                      B, DIMC, bias, nullptr,
                      out + (size_t)blockIdx.x * 128 * K3, K3);
}

// ======================================================================
// resize + concat (unchanged, passing)
// ======================================================================
__global__ void __launch_bounds__(256)
resize_concat_kernel(const float* __restrict__ l,
                     const float* __restrict__ mid,
                     const float* __restrict__ s,
                     float* __restrict__ xcat)
{
    __shared__ float st[64 * 65];
    const int bh = blockIdx.x;
    const int b = bh >> 6, h = bh & 63;
    const int tid = threadIdx.x;
    const int wq = tid & 63;
    const int cl = tid >> 6;

    int ljh[4]; float lwh[4];
    int ljw[4]; float lww[4];
    {
        float sum = 0.f;
#pragma unroll
        for (int t = 0; t < 4; t++) {
            int jj = 2*h - 1 + t;
            float r = (t == 0 || t == 3) ? 0.25f : 0.75f;
            bool ok = (jj >= 0 && jj < 128);
            ljh[t] = ok ? jj : 0;
            lwh[t] = ok ? r : 0.f;
            sum += lwh[t];
        }
        float inv = 1.f / sum;
#pragma unroll
        for (int t = 0; t < 4; t++) lwh[t] *= inv;
    }
    {
        float sum = 0.f;
#pragma unroll
        for (int t = 0; t < 4; t++) {
            int jj = 2*wq - 1 + t;
            float r = (t == 0 || t == 3) ? 0.25f : 0.75f;
            bool ok = (jj >= 0 && jj < 128);
            ljw[t] = ok ? jj : 0;
            lww[t] = ok ? r : 0.f;
            sum += lww[t];
        }
        float inv = 1.f / sum;
#pragma unroll
        for (int t = 0; t < 4; t++) lww[t] *= inv;
    }
    int sjh[2]; float swh[2];
    int sjw[2]; float sww[2];
    {
        float p = 0.5f*h - 0.25f;
        int j0 = (int)floorf(p);
        float f = p - (float)j0;
        bool o0 = (j0 >= 0 && j0 < 32), o1 = (j0+1 >= 0 && j0+1 < 32);
        swh[0] = o0 ? (1.f - f) : 0.f; sjh[0] = o0 ? j0 : 0;
        swh[1] = o1 ? f : 0.f;         sjh[1] = o1 ? (j0+1) : 0;
        float inv = 1.f / (swh[0] + swh[1]);
        swh[0] *= inv; swh[1] *= inv;
    }
    {
        float p = 0.5f*wq - 0.25f;
        int j0 = (int)floorf(p);
        float f = p - (float)j0;
        bool o0 = (j0 >= 0 && j0 < 32), o1 = (j0+1 >= 0 && j0+1 < 32);
        sww[0] = o0 ? (1.f - f) : 0.f; sjw[0] = o0 ? j0 : 0;
        sww[1] = o1 ? f : 0.f;         sjw[1] = o1 ? (j0+1) : 0;
        float inv = 1.f / (sww[0] + sww[1]);
        sww[0] *= inv; sww[1] *= inv;
    }

    const int ww = tid >> 2;
    const int c0 = (tid & 3) * 16;

#pragma unroll 1
    for (int chunk = 0; chunk < 6; chunk++) {
        const int cbase = chunk * 64;
        if (chunk < 2) {
#pragma unroll 4
            for (int i = 0; i < 16; i++) {
                int c = cbase + cl + 4*i;
                const float* lp = l + ((size_t)(b*128 + c) << 14);
                float v = 0.f;
#pragma unroll
                for (int a = 0; a < 4; a++) {
                    const float* row = lp + (ljh[a] << 7);
                    float ra = lww[0]*row[ljw[0]] + lww[1]*row[ljw[1]]
                             + lww[2]*row[ljw[2]] + lww[3]*row[ljw[3]];
                    v = fmaf(lwh[a], ra, v);
                }
                st[(cl + 4*i) * 65 + wq] = v;
            }
        } else if (chunk < 4) {
#pragma unroll 4
            for (int i = 0; i < 16; i++) {
                int c = cbase - 128 + cl + 4*i;
                st[(cl + 4*i) * 65 + wq] =
                    mid[((size_t)(b*128 + c) << 12) + (h << 6) + wq];
            }
        } else {
#pragma unroll 4
            for (int i = 0; i < 16; i++) {
                int c = cbase - 256 + cl + 4*i;
                const float* sp = s + ((size_t)(b*128 + c) << 10);
                const float* r0 = sp + (sjh[0] << 5);
                const float* r1 = sp + (sjh[1] << 5);
                float v = swh[0]*(sww[0]*r0[sjw[0]] + sww[1]*r0[sjw[1]])
                        + swh[1]*(sww[0]*r1[sjw[0]] + sww[1]*r1[sjw[1]]);
                st[(cl + 4*i) * 65 + wq] = v;
            }
        }
        __syncthreads();
        float* dst = xcat + (size_t)(bh*64 + ww) * K3 + cbase + c0;
#pragma unroll
        for (int j = 0; j < 4; j++) {
            int cc = c0 + 4*j;
            float4 v = make_float4(st[(cc+0)*65 + ww], st[(cc+1)*65 + ww],
                                   st[(cc+2)*65 + ww], st[(cc+3)*65 + ww]);
            *(float4*)(dst + 4*j) = v;
        }
        __syncthreads();
    }
}

// ======================================================================
// Scan kernel v4b: tensor-core GRU, 24 warps (768 thr), 16 gates/warp.
// (scalar sg stores — float2 at stride-9 rows is misaligned)
// ======================================================================
#define W_OFF_LO 104448
#define H_OFF_HI 208896
#define H_OFF_LO 211072
#define SG_OFF   213248
#define SCAN_SMEM (SG_OFF + 384*9*4)   // 227,072 bytes

__global__ void __launch_bounds__(768, 1)
scan_kernel(const float* __restrict__ whh_h,
            const float* __restrict__ bhh_h,
            const float* __restrict__ whh_w,
            const float* __restrict__ bhh_w,
            const float* __restrict__ gxh,
            const float* __restrict__ gxw,
            float* __restrict__ ohp,
            float* __restrict__ owp)
{
    extern __shared__ char smraw[];
    __nv_bfloat16* w_hi = (__nv_bfloat16*)(smraw);              // [384][136]
    __nv_bfloat16* w_lo = (__nv_bfloat16*)(smraw + W_OFF_LO);
    __nv_bfloat16* h_hi = (__nv_bfloat16*)(smraw + H_OFF_HI);   // [8][136]
    __nv_bfloat16* h_lo = (__nv_bfloat16*)(smraw + H_OFF_LO);
    float* sg = (float*)(smraw + SG_OFF);                       // [384][9]

    const uint32_t sbase = smem_u32(smraw);
    const uint32_t u_w_hi = sbase;
    const uint32_t u_w_lo = sbase + W_OFF_LO;
    const uint32_t u_h_hi = sbase + H_OFF_HI;
    const uint32_t u_h_lo = sbase + H_OFF_LO;

    const int dir = blockIdx.x >> 6;
    const int sub = blockIdx.x & 63;
    const int b   = sub >> 3;
    const int q0  = (sub & 7) << 3;

    const float* whh = dir ? whh_w : whh_h;
    const float* bhh = dir ? bhh_w : bhh_h;
    const float* gx  = dir ? gxw : gxh;
    float* outp      = dir ? owp : ohp;

    const int tid  = threadIdx.x;
    const int lane = tid & 31;
    const int wrp  = tid >> 5;          // 0..23, gate base = wrp*16

    // ---- stage W hi/lo (coalesced; warp stages its own 16 rows) ----
    {
        const int col4 = lane * 4;
#pragma unroll
        for (int j = 0; j < 16; j++) {
            int r = wrp * 16 + j;
            float4 v = *(const float4*)(whh + (size_t)r * 128 + col4);
            uint2 hi, lo; cvt4(v, hi, lo);
            *(uint2*)(w_hi + r * SA_STRIDE + col4) = hi;
            *(uint2*)(w_lo + r * SA_STRIDE + col4) = lo;
        }
    }
    // ---- zero h bufs (incl. padding) ----
    for (int i = tid; i < 8 * SA_STRIDE; i += 768) {
        h_hi[i] = __ushort_as_bfloat16((unsigned short)0);
        h_lo[i] = __ushort_as_bfloat16((unsigned short)0);
    }

    // ---- tail-role setup (tid < 256) ----
    const int c  = tid & 127;
    const int sh = (tid >> 7) & 1;
    float hreg[4];
    float bh_r = 0.f, bh_z = 0.f, bh_n = 0.f;
    if (tid < 256) {
#pragma unroll
        for (int j = 0; j < 4; j++) hreg[j] = 0.f;
        bh_r = bhh[c];
        bh_z = bhh[c + 128];
        bh_n = bhh[c + 256];
    }
    __syncthreads();

#define PIXAT(t, s2) (dir ? ((b*64 + q0+(s2))*64 + (t)) : ((b*64 + (t))*64 + q0+(s2)))

    const uint32_t a_off0 = (uint32_t)(((wrp*16 + (lane & 15)) * SA_STRIDE
                                        + ((lane >> 4) << 3)) * 2);
    const uint32_t b_off  = (uint32_t)((((lane & 7) * SA_STRIDE)
                                        + (((lane >> 3) & 1) << 3)) * 2);
    const int grow = wrp*16 + (lane >> 2);
    const int scol = (lane & 3) * 2;

    for (int t = 0; t < 64; t++) {
        float gr[4], gz[4], gn[4];
        if (tid < 256) {
#pragma unroll
            for (int j = 0; j < 4; j++) {
                const float* base = gx + (size_t)PIXAT(t, sh*4 + j) * K3;
                gr[j] = base[c];
                gz[j] = base[128 + c];
                gn[j] = base[256 + c];
            }
        }

        // ---- mma phase: one m16 tile per warp ----
        float acc[4];
        acc[0] = acc[1] = acc[2] = acc[3] = 0.f;
#pragma unroll
        for (int ch = 0; ch < 8; ch++) {
            const uint32_t kb = (uint32_t)(ch * 32);
            uint32_t bh2[2], bl2[2];
            ldsm2(bh2, u_h_hi + b_off + kb);
            ldsm2(bl2, u_h_lo + b_off + kb);
            uint32_t ah[4], al[4];
            ldsm4(ah, u_w_hi + a_off0 + kb);
            ldsm4(al, u_w_lo + a_off0 + kb);
            mma16816(acc, ah, bh2);
            mma16816(acc, ah, bl2);
            mma16816(acc, al, bh2);
        }
        sg[grow*9 + scol]       = acc[0];
        sg[grow*9 + scol + 1]   = acc[1];
        sg[(grow+8)*9 + scol]     = acc[2];
        sg[(grow+8)*9 + scol + 1] = acc[3];
        __syncthreads();

        // ---- tail: nonlinearity + h update (4 seqs/thread) ----
        if (tid < 256) {
#pragma unroll
            for (int j = 0; j < 4; j++) {
                int s2 = sh*4 + j;
                float rp = sg[c*9 + s2]       + bh_r + gr[j];
                float zp = sg[(c+128)*9 + s2] + bh_z + gz[j];
                float sn = sg[(c+256)*9 + s2] + bh_n;
                float er = __expf(-rp);
                float ez = __expf(-zp);
                float r = __fdividef(1.f, 1.f + er);
                float z = __fdividef(1.f, 1.f + ez);
                float xn = gn[j] + r * sn;
                float en = __expf(2.f * xn);
                float n = 1.f - __fdividef(2.f, en + 1.f);
                float hnew = (1.f - z) * n + z * hreg[j];
                hreg[j] = hnew;
                unsigned short hb = __bfloat16_as_ushort(__float2bfloat16(hnew));
                float lr = hnew - __uint_as_float((uint32_t)hb << 16);
                unsigned short lb = __bfloat16_as_ushort(__float2bfloat16(lr));
                h_hi[s2 * SA_STRIDE + c] = __ushort_as_bfloat16(hb);
                h_lo[s2 * SA_STRIDE + c] = __ushort_as_bfloat16(lb);
                outp[(size_t)PIXAT(t, s2) * DIMC + c] = hnew;
            }
        }
        __syncthreads();
    }
#undef PIXAT
}

// ======================================================================
// Tail kernel v2: bf16x3 tensor-core. One block = 128 pixels.
// GEMM1(gate_w) -> sigmoid*s re-staged -> GEMM2(pw) -> affine/relu +
// residual -> channel-major store (staging aliases B-tile smem).
// ======================================================================
#define TAILM_SMEM 139264

__global__ void __launch_bounds__(256)
tail_kernel(const float* __restrict__ ohp,
            const float* __restrict__ owp,
            const float* __restrict__ xres,
            const float* __restrict__ gate_w,
            const float* __restrict__ gate_b,
            const float* __restrict__ pw,
            const float* __restrict__ pscale,
            const float* __restrict__ pshift,
            float* __restrict__ out)
{
    extern __shared__ char smraw[];
    __nv_bfloat16* a_hi = (__nv_bfloat16*)(smraw);
    __nv_bfloat16* a_lo = (__nv_bfloat16*)(smraw + 34816);
    __nv_bfloat16* b_hi = (__nv_bfloat16*)(smraw + 69632);
    __nv_bfloat16* b_lo = (__nv_bfloat16*)(smraw + 104448);
    float* st = (float*)(smraw + 69632);          // aliases B region (post-GEMM2)
    const uint32_t sbase = smem_u32(smraw);
    const uint32_t u_a_hi = sbase;
    const uint32_t u_a_lo = sbase + 34816;
    const uint32_t u_b_hi = sbase + 69632;
    const uint32_t u_b_lo = sbase + 104448;

    const int m0  = blockIdx.x * 128;
    const int b   = m0 >> 12;
    const int hw0 = m0 & 4095;
    const int tid = threadIdx.x;
    const int wid = tid >> 5;
    const int lane = tid & 31;
    const int wm = wid >> 1;          // 0..3 (32 rows)
    const int wn = wid & 1;           // 0..1 (64 cols)
    const int gid = lane >> 2, tig = lane & 3;
    const int col4 = lane * 4;
    const int rbase = wid;            // 0..7

    // ---- stage A = oh+ow, B = gate_w ----
#pragma unroll
    for (int j = 0; j < 16; j++) {
        int r = rbase + 8 * j;
        float4 a = *(const float4*)(ohp + (size_t)(m0 + r) * DIMC + col4);
        float4 c = *(const float4*)(owp + (size_t)(m0 + r) * DIMC + col4);
        float4 v = make_float4(a.x + c.x, a.y + c.y, a.z + c.z, a.w + c.w);
        uint2 hi, lo; cvt4(v, hi, lo);
        *(uint2*)(a_hi + r * SA_STRIDE + col4) = hi;
        *(uint2*)(a_lo + r * SA_STRIDE + col4) = lo;
        float4 w = *(const float4*)(gate_w + (size_t)r * 128 + col4);
        cvt4(w, hi, lo);
        *(uint2*)(b_hi + r * SA_STRIDE + col4) = hi;
        *(uint2*)(b_lo + r * SA_STRIDE + col4) = lo;
    }
    __syncthreads();

    const uint32_t a_off0 = (uint32_t)(((wm*32 + (lane & 15)) * SA_STRIDE
                                        + ((lane >> 4) << 3)) * 2);
    const uint32_t b_row0 = (uint32_t)(wn*64 + (lane & 7) + ((lane >> 4) << 3));
    const uint32_t b_col8 = (uint32_t)(((lane >> 3) & 1) << 3);

    // ================= GEMM1 =================
    float acc[2][8][4];
#pragma unroll
    for (int i = 0; i < 2; i++)
#pragma unroll
        for (int j = 0; j < 8; j++)
#pragma unroll
            for (int e = 0; e < 4; e++) acc[i][j][e] = 0.f;

#pragma unroll
    for (int ch = 0; ch < 8; ch++) {
        const int k = ch * 16;
        uint32_t ah[2][4], al[2][4];
#pragma unroll
        for (int i = 0; i < 2; i++) {
            uint32_t off = a_off0 + (uint32_t)((i*16*SA_STRIDE + k) * 2);
            ldsm4(ah[i], u_a_hi + off);
            ldsm4(al[i], u_a_lo + off);
        }
        uint32_t bh[8][2], bl[8][2];
#pragma unroll
        for (int nb = 0; nb < 4; nb++) {
            uint32_t off = (uint32_t)(((b_row0 + nb*16) * SA_STRIDE + k + b_col8) * 2);
            uint32_t r[4];
            ldsm4(r, u_b_hi + off);
            bh[2*nb][0] = r[0]; bh[2*nb][1] = r[1];
            bh[2*nb+1][0] = r[2]; bh[2*nb+1][1] = r[3];
            ldsm4(r, u_b_lo + off);
            bl[2*nb][0] = r[0]; bl[2*nb][1] = r[1];
            bl[2*nb+1][0] = r[2]; bl[2*nb+1][1] = r[3];
        }
#pragma unroll
        for (int i = 0; i < 2; i++)
#pragma unroll
            for (int j = 0; j < 8; j++) {
                mma16816(acc[i][j], ah[i], bh[j]);
                mma16816(acc[i][j], ah[i], bl[j]);
                mma16816(acc[i][j], al[i], bh[j]);
            }
    }
    __syncthreads();   // done reading A(s) and B(gate_w)

    // ---- gated = s * sigmoid(gate+gb); overwrite A region; stage pw in B ----
#pragma unroll
    for (int i = 0; i < 2; i++) {
        int mrow = wm*32 + i*16 + gid;
#pragma unroll
        for (int j = 0; j < 8; j++) {
            int ncol = wn*64 + j*8 + tig*2;
            float2 gb2 = *(const float2*)(gate_b + ncol);
#pragma unroll
            for (int rr = 0; rr < 2; rr++) {
                int m = mrow + rr*8;
#pragma unroll
                for (int e = 0; e < 2; e++) {
                    int n = ncol + e;
                    float gv = acc[i][j][rr*2 + e] + (e ? gb2.y : gb2.x);
                    float sig = __fdividef(1.f, 1.f + __expf(-gv));
                    float sval = __bfloat162float(a_hi[m*SA_STRIDE + n])
                               + __bfloat162float(a_lo[m*SA_STRIDE + n]);
                    float gt = sval * sig;
                    unsigned short hb = __bfloat16_as_ushort(__float2bfloat16(gt));
                    float lr = gt - __uint_as_float((uint32_t)hb << 16);
                    unsigned short lb = __bfloat16_as_ushort(__float2bfloat16(lr));
                    a_hi[m*SA_STRIDE + n] = __ushort_as_bfloat16(hb);
                    a_lo[m*SA_STRIDE + n] = __ushort_as_bfloat16(lb);
                }
            }
        }
    }
#pragma unroll
    for (int j = 0; j < 16; j++) {
        int r = rbase + 8 * j;
        float4 w = *(const float4*)(pw + (size_t)r * 128 + col4);
        uint2 hi, lo; cvt4(w, hi, lo);
        *(uint2*)(b_hi + r * SA_STRIDE + col4) = hi;
        *(uint2*)(b_lo + r * SA_STRIDE + col4) = lo;
    }
    __syncthreads();

    // ================= GEMM2 =================
    float acc2[2][8][4];
#pragma unroll
    for (int i = 0; i < 2; i++)
#pragma unroll
        for (int j = 0; j < 8; j++)
#pragma unroll
            for (int e = 0; e < 4; e++) acc2[i][j][e] = 0.f;

#pragma unroll
    for (int ch = 0; ch < 8; ch++) {
        const int k = ch * 16;
        uint32_t ah[2][4], al[2][4];
#pragma unroll
        for (int i = 0; i < 2; i++) {
            uint32_t off = a_off0 + (uint32_t)((i*16*SA_STRIDE + k) * 2);
            ldsm4(ah[i], u_a_hi + off);
            ldsm4(al[i], u_a_lo + off);
        }
        uint32_t bh[8][2], bl[8][2];
#pragma unroll
        for (int nb = 0; nb < 4; nb++) {
            uint32_t off = (uint32_t)(((b_row0 + nb*16) * SA_STRIDE + k + b_col8) * 2);
            uint32_t r[4];
            ldsm4(r, u_b_hi + off);
            bh[2*nb][0] = r[0]; bh[2*nb][1] = r[1];
            bh[2*nb+1][0] = r[2]; bh[2*nb+1][1] = r[3];
            ldsm4(r, u_b_lo + off);
            bl[2*nb][0] = r[0]; bl[2*nb][1] = r[1];
            bl[2*nb+1][0] = r[2]; bl[2*nb+1][1] = r[3];
        }
#pragma unroll
        for (int i = 0; i < 2; i++)
#pragma unroll
            for (int j = 0; j < 8; j++) {
                mma16816(acc2[i][j], ah[i], bh[j]);
                mma16816(acc2[i][j], ah[i], bl[j]);
                mma16816(acc2[i][j], al[i], bh[j]);
            }
    }
    __syncthreads();   // B region free -> becomes st

    // ---- epilogue: affine/relu + residual -> st[c][128+pad] ----
#pragma unroll
    for (int i = 0; i < 2; i++) {
        int mrow = wm*32 + i*16 + gid;
#pragma unroll
        for (int j = 0; j < 8; j++) {
            int ncol = wn*64 + j*8 + tig*2;
            float2 q0 = *(const float2*)(pscale + ncol);
            float2 q1 = *(const float2*)(pshift + ncol);
#pragma unroll
            for (int rr = 0; rr < 2; rr++) {
                int m = mrow + rr*8;
                float2 xr = *(const float2*)(xres + (size_t)(m0 + m) * DIMC + ncol);
                float v0 = fmaxf(fmaf(acc2[i][j][rr*2+0], q0.x, q1.x), 0.f) + xr.x;
                float v1 = fmaxf(fmaf(acc2[i][j][rr*2+1], q0.y, q1.y), 0.f) + xr.y;
                st[(ncol+0)*132 + m] = v0;
                st[(ncol+1)*132 + m] = v1;
            }
        }
    }
    __syncthreads();

    // ---- coalesced channel-major store ----
    for (int i = tid; i < 128*128; i += 256) {
        int cc = i >> 7, p = i & 127;
        out[(size_t)(b*128 + cc)*HW + hw0 + p] = st[cc*132 + p];
    }
}

// ======================================================================
// Launch
// ======================================================================
extern "C" void kernel_launch(void* const* d_in, const int* in_sizes, int n_in,
                              void* d_out, int out_size)
{
    const float* l     = (const float*)d_in[0];
    const float* m_    = (const float*)d_in[1];
    const float* s_    = (const float*)d_in[2];
    const float* piw   = (const float*)d_in[3];
    const float* pisc  = (const float*)d_in[4];
    const float* pish  = (const float*)d_in[5];
    const float* wih_h = (const float*)d_in[6];
    const float* whh_h = (const float*)d_in[7];
    const float* bih_h = (const float*)d_in[8];
    const float* bhh_h = (const float*)d_in[9];
    const float* wih_w = (const float*)d_in[10];
    const float* whh_w = (const float*)d_in[11];
    const float* bih_w = (const float*)d_in[12];
    const float* bhh_w = (const float*)d_in[13];
    const float* gw    = (const float*)d_in[14];
    const float* gb    = (const float*)d_in[15];
    const float* pow_  = (const float*)d_in[16];
    const float* posc  = (const float*)d_in[17];
    const float* posh  = (const float*)d_in[18];
    float* out = (float*)d_out;

    void *p_xcat, *p_x, *p_gxh, *p_gxw, *p_oh, *p_ow;
    cudaGetSymbolAddress(&p_xcat, g_xcat);
    cudaGetSymbolAddress(&p_x,    g_x);
    cudaGetSymbolAddress(&p_gxh,  g_gxh);
    cudaGetSymbolAddress(&p_gxw,  g_gxw);
    cudaGetSymbolAddress(&p_oh,   g_oh);
    cudaGetSymbolAddress(&p_ow,   g_ow);
    float* xcat = (float*)p_xcat;
    float* x    = (float*)p_x;
    float* gxh  = (float*)p_gxh;
    float* gxw  = (float*)p_gxw;
    float* oh   = (float*)p_oh;
    float* ow   = (float*)p_ow;

    cudaFuncSetAttribute(mma_proj_kernel, cudaFuncAttributeMaxDynamicSharedMemorySize, MMA_SMEM);
    cudaFuncSetAttribute(mma_gx_kernel,   cudaFuncAttributeMaxDynamicSharedMemorySize, MMA_SMEM);
    cudaFuncSetAttribute(scan_kernel,     cudaFuncAttributeMaxDynamicSharedMemorySize, SCAN_SMEM);
    cudaFuncSetAttribute(tail_kernel,     cudaFuncAttributeMaxDynamicSharedMemorySize, TAILM_SMEM);

    // 1. resize + concat
    resize_concat_kernel<<<BATCH*HGT, 256>>>(l, m_, s_, xcat);

    // 2. proj_in (bf16x3 warp MMA)
    mma_proj_kernel<<<M_TOT/128, 256, MMA_SMEM>>>(xcat, piw, pisc, pish, x);

    // 3. gx for both directions (bf16x3 warp MMA)
    mma_gx_kernel<<<dim3(M_TOT/128, 2), 256, MMA_SMEM>>>(x, wih_h, bih_h, wih_w, bih_w, gxh, gxw);

    // 4. both GRU scans (tensor-core recurrent matvec, 24 warps)
    scan_kernel<<<128, 768, SCAN_SMEM>>>(whh_h, bhh_h, whh_w, bhh_w, gxh, gxw, oh, ow);

    // 5. gate + proj_out + residual (bf16x3 tensor-core) + transposed store
    tail_kernel<<<M_TOT/128, 256, TAILM_SMEM>>>(oh, ow, x, gw, gb, pow_, posc, posh, out);
}

// round 10
// speedup vs baseline: 2.6719x; 1.1520x over previous
#include <cuda_runtime.h>
#include <cuda_bf16.h>
#include <math.h>
#include <stdint.h>

// ---------------- problem constants ----------------
#define BATCH 8
#define DIMC 128
#define HGT 64
#define WID 64
#define HW 4096
#define M_TOT 32768       // BATCH*HGT*WID
#define K3 384

// ---------------- scratch ----------------
__device__ float g_xcat[M_TOT * K3];
__device__ float g_x[M_TOT * DIMC];
__device__ float g_gxh[M_TOT * K3];
__device__ float g_gxw[M_TOT * K3];
__device__ float g_oh[M_TOT * DIMC];
__device__ float g_ow[M_TOT * DIMC];

// ======================================================================
// helpers
// ======================================================================
__device__ __forceinline__ uint32_t smem_u32(const void* p) {
    uint32_t a;
    asm("{ .reg .u64 t; cvta.to.shared.u64 t, %1; cvt.u32.u64 %0, t; }"
        : "=r"(a) : "l"(p));
    return a;
}

__device__ __forceinline__ void ldsm4(uint32_t* r, uint32_t addr) {
    asm volatile("ldmatrix.sync.aligned.m8n8.x4.shared.b16 {%0,%1,%2,%3}, [%4];"
                 : "=r"(r[0]), "=r"(r[1]), "=r"(r[2]), "=r"(r[3]) : "r"(addr));
}

__device__ __forceinline__ void ldsm2(uint32_t* r, uint32_t addr) {
    asm volatile("ldmatrix.sync.aligned.m8n8.x2.shared.b16 {%0,%1}, [%2];"
                 : "=r"(r[0]), "=r"(r[1]) : "r"(addr));
}

__device__ __forceinline__ void mma16816(float* c, const uint32_t* a, const uint32_t* b) {
    asm volatile(
        "mma.sync.aligned.m16n8k16.row.col.f32.bf16.bf16.f32 "
        "{%0,%1,%2,%3}, {%4,%5,%6,%7}, {%8,%9}, {%0,%1,%2,%3};"
        : "+f"(c[0]), "+f"(c[1]), "+f"(c[2]), "+f"(c[3])
        : "r"(a[0]), "r"(a[1]), "r"(a[2]), "r"(a[3]), "r"(b[0]), "r"(b[1]));
}

// convert float4 -> bf16 hi pair + bf16 lo-residual pair
__device__ __forceinline__ void cvt4(float4 v, uint2& hi, uint2& lo) {
    unsigned short b0 = __bfloat16_as_ushort(__float2bfloat16(v.x));
    unsigned short b1 = __bfloat16_as_ushort(__float2bfloat16(v.y));
    unsigned short b2 = __bfloat16_as_ushort(__float2bfloat16(v.z));
    unsigned short b3 = __bfloat16_as_ushort(__float2bfloat16(v.w));
    hi.x = ((uint32_t)b1 << 16) | (uint32_t)b0;
    hi.y = ((uint32_t)b3 << 16) | (uint32_t)b2;
    float r0 = v.x - __uint_as_float((uint32_t)b0 << 16);
    float r1 = v.y - __uint_as_float((uint32_t)b1 << 16);
    float r2 = v.z - __uint_as_float((uint32_t)b2 << 16);
    float r3 = v.w - __uint_as_float((uint32_t)b3 << 16);
    unsigned short c0 = __bfloat16_as_ushort(__float2bfloat16(r0));
    unsigned short c1 = __bfloat16_as_ushort(__float2bfloat16(r1));
    unsigned short c2 = __bfloat16_as_ushort(__float2bfloat16(r2));
    unsigned short c3 = __bfloat16_as_ushort(__float2bfloat16(r3));
    lo.x = ((uint32_t)c1 << 16) | (uint32_t)c0;
    lo.y = ((uint32_t)c3 << 16) | (uint32_t)c2;
}

// ======================================================================
// bf16x3 warp-MMA NT GEMM core (device fn, shared smem layout)
// ======================================================================
#define SA_STRIDE 136
#define MMA_SMEM (104448)

template<int KSLABS, int NTILES, int EPI>
__device__ void mma_core(const float* __restrict__ A0, int lda,
                         const float* __restrict__ B0, int ldb,
                         const float* __restrict__ p0, const float* __restrict__ p1,
                         float* __restrict__ C0, int ldc)
{
    extern __shared__ char smraw[];
    __nv_bfloat16* sa_hi = (__nv_bfloat16*)(smraw);
    __nv_bfloat16* sa_lo = (__nv_bfloat16*)(smraw + 34816);
    __nv_bfloat16* sb_hi = (__nv_bfloat16*)(smraw + 69632);
    __nv_bfloat16* sb_lo = (__nv_bfloat16*)(smraw + 87040);
    const uint32_t sbase = smem_u32(smraw);
    const uint32_t u_sa_hi = sbase;
    const uint32_t u_sa_lo = sbase + 34816;
    const uint32_t u_sb_hi = sbase + 69632;
    const uint32_t u_sb_lo = sbase + 87040;

    const int tid  = threadIdx.x;
    const int wid  = tid >> 5;
    const int lane = tid & 31;
    const int wm = wid >> 1;
    const int wn = wid & 1;
    const int gid = lane >> 2, tig = lane & 3;
    const int col4 = (tid & 31) * 4;
    const int rbase = tid >> 5;

#pragma unroll 1
    for (int nt = 0; nt < NTILES; nt++) {
        float acc[2][4][4];
#pragma unroll
        for (int i = 0; i < 2; i++)
#pragma unroll
            for (int j = 0; j < 4; j++)
#pragma unroll
                for (int e = 0; e < 4; e++) acc[i][j][e] = 0.f;

#pragma unroll 1
        for (int s = 0; s < KSLABS; s++) {
            __syncthreads();
            if (nt == 0 || KSLABS > 1) {
#pragma unroll
                for (int j = 0; j < 16; j++) {
                    int r = rbase + 8 * j;
                    float4 v = *(const float4*)(A0 + (size_t)r * lda + s * 128 + col4);
                    uint2 hi, lo; cvt4(v, hi, lo);
                    *(uint2*)(sa_hi + r * SA_STRIDE + col4) = hi;
                    *(uint2*)(sa_lo + r * SA_STRIDE + col4) = lo;
                }
            }
            {
#pragma unroll
                for (int j = 0; j < 8; j++) {
                    int r = rbase + 8 * j;
                    float4 v = *(const float4*)(B0 + (size_t)(nt * 64 + r) * ldb + s * 128 + col4);
                    uint2 hi, lo; cvt4(v, hi, lo);
                    *(uint2*)(sb_hi + r * SA_STRIDE + col4) = hi;
                    *(uint2*)(sb_lo + r * SA_STRIDE + col4) = lo;
                }
            }
            __syncthreads();

#pragma unroll
            for (int ch = 0; ch < 8; ch++) {
                const int k = ch * 16;
                uint32_t ah[2][4], al[2][4];
#pragma unroll
                for (int i = 0; i < 2; i++) {
                    uint32_t off = (uint32_t)(((wm*32 + i*16 + (lane & 15)) * SA_STRIDE
                                               + k + ((lane >> 4) << 3)) * 2);
                    ldsm4(ah[i], u_sa_hi + off);
                    ldsm4(al[i], u_sa_lo + off);
                }
                uint32_t bh[4][2], bl[4][2];
#pragma unroll
                for (int nb = 0; nb < 2; nb++) {
                    int row = wn*32 + nb*16 + (lane & 7) + ((lane >> 4) << 3);
                    int col = k + ((lane >> 3) & 1) * 8;
                    uint32_t off = (uint32_t)((row * SA_STRIDE + col) * 2);
                    uint32_t r[4];
                    ldsm4(r, u_sb_hi + off);
                    bh[2*nb][0] = r[0]; bh[2*nb][1] = r[1];
                    bh[2*nb+1][0] = r[2]; bh[2*nb+1][1] = r[3];
                    ldsm4(r, u_sb_lo + off);
                    bl[2*nb][0] = r[0]; bl[2*nb][1] = r[1];
                    bl[2*nb+1][0] = r[2]; bl[2*nb+1][1] = r[3];
                }
#pragma unroll
                for (int i = 0; i < 2; i++)
#pragma unroll
                    for (int j = 0; j < 4; j++) {
                        mma16816(acc[i][j], ah[i], bh[j]);
                        mma16816(acc[i][j], ah[i], bl[j]);
                        mma16816(acc[i][j], al[i], bh[j]);
                    }
            }
        }

#pragma unroll
        for (int i = 0; i < 2; i++) {
            int mrow = wm*32 + i*16 + gid;
#pragma unroll
            for (int j = 0; j < 4; j++) {
                int ncol = nt*64 + wn*32 + j*8 + tig*2;
                float2 q0 = *(const float2*)(p0 + ncol);
                float2 q1 = (EPI == 0) ? *(const float2*)(p1 + ncol)
                                       : make_float2(0.f, 0.f);
                float v0, v1, v2, v3;
                if (EPI == 0) {
                    v0 = fmaxf(fmaf(acc[i][j][0], q0.x, q1.x), 0.f);
                    v1 = fmaxf(fmaf(acc[i][j][1], q0.y, q1.y), 0.f);
                    v2 = fmaxf(fmaf(acc[i][j][2], q0.x, q1.x), 0.f);
                    v3 = fmaxf(fmaf(acc[i][j][3], q0.y, q1.y), 0.f);
                } else {
                    v0 = acc[i][j][0] + q0.x;
                    v1 = acc[i][j][1] + q0.y;
                    v2 = acc[i][j][2] + q0.x;
                    v3 = acc[i][j][3] + q0.y;
                }
                *(float2*)(C0 + (size_t)mrow * ldc + ncol) = make_float2(v0, v1);
                *(float2*)(C0 + (size_t)(mrow + 8) * ldc + ncol) = make_float2(v2, v3);
            }
        }
    }
}

// ======================================================================
// gx phase: A = x (staged once), 12 n-tiles over both directions
// ======================================================================
__device__ void gx_phase(const float* __restrict__ X0,
                         const float* __restrict__ wih_h, const float* __restrict__ bih_h,
                         const float* __restrict__ wih_w, const float* __restrict__ bih_w,
                         float* __restrict__ gxh, float* __restrict__ gxw)
{
    extern __shared__ char smraw[];
    __nv_bfloat16* sa_hi = (__nv_bfloat16*)(smraw);
    __nv_bfloat16* sa_lo = (__nv_bfloat16*)(smraw + 34816);
    __nv_bfloat16* sb_hi = (__nv_bfloat16*)(smraw + 69632);
    __nv_bfloat16* sb_lo = (__nv_bfloat16*)(smraw + 87040);
    const uint32_t sbase = smem_u32(smraw);
    const uint32_t u_sa_hi = sbase;
    const uint32_t u_sa_lo = sbase + 34816;
    const uint32_t u_sb_hi = sbase + 69632;
    const uint32_t u_sb_lo = sbase + 87040;

    const int tid  = threadIdx.x;
    const int wid  = tid >> 5;
    const int lane = tid & 31;
    const int wm = wid >> 1;
    const int wn = wid & 1;
    const int gid = lane >> 2, tig = lane & 3;
    const int col4 = lane * 4;
    const int rbase = wid;

    // stage A = x (once)
#pragma unroll
    for (int j = 0; j < 16; j++) {
        int r = rbase + 8 * j;
        float4 v = *(const float4*)(X0 + (size_t)r * DIMC + col4);
        uint2 hi, lo; cvt4(v, hi, lo);
        *(uint2*)(sa_hi + r * SA_STRIDE + col4) = hi;
        *(uint2*)(sa_lo + r * SA_STRIDE + col4) = lo;
    }

#pragma unroll 1
    for (int nt = 0; nt < 12; nt++) {
        const bool hdir = (nt < 6);
        const int ntl = hdir ? nt : nt - 6;
        const float* B0   = hdir ? wih_h : wih_w;
        const float* bias = hdir ? bih_h : bih_w;
        float* C0         = hdir ? gxh : gxw;

        __syncthreads();
#pragma unroll
        for (int j = 0; j < 8; j++) {
            int r = rbase + 8 * j;
            float4 v = *(const float4*)(B0 + (size_t)(ntl * 64 + r) * DIMC + col4);
            uint2 hi, lo; cvt4(v, hi, lo);
            *(uint2*)(sb_hi + r * SA_STRIDE + col4) = hi;
            *(uint2*)(sb_lo + r * SA_STRIDE + col4) = lo;
        }
        __syncthreads();

        float acc[2][4][4];
#pragma unroll
        for (int i = 0; i < 2; i++)
#pragma unroll
            for (int j = 0; j < 4; j++)
#pragma unroll
                for (int e = 0; e < 4; e++) acc[i][j][e] = 0.f;

#pragma unroll
        for (int ch = 0; ch < 8; ch++) {
            const int k = ch * 16;
            uint32_t ah[2][4], al[2][4];
#pragma unroll
            for (int i = 0; i < 2; i++) {
                uint32_t off = (uint32_t)(((wm*32 + i*16 + (lane & 15)) * SA_STRIDE
                                           + k + ((lane >> 4) << 3)) * 2);
                ldsm4(ah[i], u_sa_hi + off);
                ldsm4(al[i], u_sa_lo + off);
            }
            uint32_t bh[4][2], bl[4][2];
#pragma unroll
            for (int nb = 0; nb < 2; nb++) {
                int row = wn*32 + nb*16 + (lane & 7) + ((lane >> 4) << 3);
                int col = k + ((lane >> 3) & 1) * 8;
                uint32_t off = (uint32_t)((row * SA_STRIDE + col) * 2);
                uint32_t r[4];
                ldsm4(r, u_sb_hi + off);
                bh[2*nb][0] = r[0]; bh[2*nb][1] = r[1];
                bh[2*nb+1][0] = r[2]; bh[2*nb+1][1] = r[3];
                ldsm4(r, u_sb_lo + off);
                bl[2*nb][0] = r[0]; bl[2*nb][1] = r[1];
                bl[2*nb+1][0] = r[2]; bl[2*nb+1][1] = r[3];
            }
#pragma unroll
            for (int i = 0; i < 2; i++)
#pragma unroll
                for (int j = 0; j < 4; j++) {
                    mma16816(acc[i][j], ah[i], bh[j]);
                    mma16816(acc[i][j], ah[i], bl[j]);
                    mma16816(acc[i][j], al[i], bh[j]);
                }
        }

#pragma unroll
        for (int i = 0; i < 2; i++) {
            int mrow = wm*32 + i*16 + gid;
#pragma unroll
            for (int j = 0; j < 4; j++) {
                int ncol = ntl*64 + wn*32 + j*8 + tig*2;
                float2 q0 = *(const float2*)(bias + ncol);
                float2 o0 = make_float2(acc[i][j][0] + q0.x, acc[i][j][1] + q0.y);
                float2 o1 = make_float2(acc[i][j][2] + q0.x, acc[i][j][3] + q0.y);
                *(float2*)(C0 + (size_t)mrow * K3 + ncol) = o0;
                *(float2*)(C0 + (size_t)(mrow + 8) * K3 + ncol) = o1;
            }
        }
    }
}

__global__ void __launch_bounds__(256, 2)
fused_projgx_kernel(const float* __restrict__ xcat,
                    const float* __restrict__ piw,
                    const float* __restrict__ pisc, const float* __restrict__ pish,
                    float* __restrict__ x,
                    const float* __restrict__ wih_h, const float* __restrict__ bih_h,
                    const float* __restrict__ wih_w, const float* __restrict__ bih_w,
                    float* __restrict__ gxh, float* __restrict__ gxw)
{
    const size_t blk = blockIdx.x;
    // phase 1: proj_in -> x
    mma_core<3, 2, 0>(xcat + blk * 128 * K3, K3, piw, K3, pisc, pish,
                      x + blk * 128 * DIMC, DIMC);
    __syncthreads();
    // phase 2: gx for both directions, A staged once
    gx_phase(x + blk * 128 * DIMC, wih_h, bih_h, wih_w, bih_w,
             gxh + blk * 128 * K3, gxw + blk * 128 * K3);
}

// ======================================================================
// resize + concat (unchanged, passing)
// ======================================================================
__global__ void __launch_bounds__(256)
resize_concat_kernel(const float* __restrict__ l,
                     const float* __restrict__ mid,
                     const float* __restrict__ s,
                     float* __restrict__ xcat)
{
    __shared__ float st[64 * 65];
    const int bh = blockIdx.x;
    const int b = bh >> 6, h = bh & 63;
    const int tid = threadIdx.x;
    const int wq = tid & 63;
    const int cl = tid >> 6;

    int ljh[4]; float lwh[4];
    int ljw[4]; float lww[4];
    {
        float sum = 0.f;
#pragma unroll
        for (int t = 0; t < 4; t++) {
            int jj = 2*h - 1 + t;
            float r = (t == 0 || t == 3) ? 0.25f : 0.75f;
            bool ok = (jj >= 0 && jj < 128);
            ljh[t] = ok ? jj : 0;
            lwh[t] = ok ? r : 0.f;
            sum += lwh[t];
        }
        float inv = 1.f / sum;
#pragma unroll
        for (int t = 0; t < 4; t++) lwh[t] *= inv;
    }
    {
        float sum = 0.f;
#pragma unroll
        for (int t = 0; t < 4; t++) {
            int jj = 2*wq - 1 + t;
            float r = (t == 0 || t == 3) ? 0.25f : 0.75f;
            bool ok = (jj >= 0 && jj < 128);
            ljw[t] = ok ? jj : 0;
            lww[t] = ok ? r : 0.f;
            sum += lww[t];
        }
        float inv = 1.f / sum;
#pragma unroll
        for (int t = 0; t < 4; t++) lww[t] *= inv;
    }
    int sjh[2]; float swh[2];
    int sjw[2]; float sww[2];
    {
        float p = 0.5f*h - 0.25f;
        int j0 = (int)floorf(p);
        float f = p - (float)j0;
        bool o0 = (j0 >= 0 && j0 < 32), o1 = (j0+1 >= 0 && j0+1 < 32);
        swh[0] = o0 ? (1.f - f) : 0.f; sjh[0] = o0 ? j0 : 0;
        swh[1] = o1 ? f : 0.f;         sjh[1] = o1 ? (j0+1) : 0;
        float inv = 1.f / (swh[0] + swh[1]);
        swh[0] *= inv; swh[1] *= inv;
    }
    {
        float p = 0.5f*wq - 0.25f;
        int j0 = (int)floorf(p);
        float f = p - (float)j0;
        bool o0 = (j0 >= 0 && j0 < 32), o1 = (j0+1 >= 0 && j0+1 < 32);
        sww[0] = o0 ? (1.f - f) : 0.f; sjw[0] = o0 ? j0 : 0;
        sww[1] = o1 ? f : 0.f;         sjw[1] = o1 ? (j0+1) : 0;
        float inv = 1.f / (sww[0] + sww[1]);
        sww[0] *= inv; sww[1] *= inv;
    }

    const int ww = tid >> 2;
    const int c0 = (tid & 3) * 16;

#pragma unroll 1
    for (int chunk = 0; chunk < 6; chunk++) {
        const int cbase = chunk * 64;
        if (chunk < 2) {
#pragma unroll 4
            for (int i = 0; i < 16; i++) {
                int c = cbase + cl + 4*i;
                const float* lp = l + ((size_t)(b*128 + c) << 14);
                float v = 0.f;
#pragma unroll
                for (int a = 0; a < 4; a++) {
                    const float* row = lp + (ljh[a] << 7);
                    float ra = lww[0]*row[ljw[0]] + lww[1]*row[ljw[1]]
                             + lww[2]*row[ljw[2]] + lww[3]*row[ljw[3]];
                    v = fmaf(lwh[a], ra, v);
                }
                st[(cl + 4*i) * 65 + wq] = v;
            }
        } else if (chunk < 4) {
#pragma unroll 4
            for (int i = 0; i < 16; i++) {
                int c = cbase - 128 + cl + 4*i;
                st[(cl + 4*i) * 65 + wq] =
                    mid[((size_t)(b*128 + c) << 12) + (h << 6) + wq];
            }
        } else {
#pragma unroll 4
            for (int i = 0; i < 16; i++) {
                int c = cbase - 256 + cl + 4*i;
                const float* sp = s + ((size_t)(b*128 + c) << 10);
                const float* r0 = sp + (sjh[0] << 5);
                const float* r1 = sp + (sjh[1] << 5);
                float v = swh[0]*(sww[0]*r0[sjw[0]] + sww[1]*r0[sjw[1]])
                        + swh[1]*(sww[0]*r1[sjw[0]] + sww[1]*r1[sjw[1]]);
                st[(cl + 4*i) * 65 + wq] = v;
            }
        }
        __syncthreads();
        float* dst = xcat + (size_t)(bh*64 + ww) * K3 + cbase + c0;
#pragma unroll
        for (int j = 0; j < 4; j++) {
            int cc = c0 + 4*j;
            float4 v = make_float4(st[(cc+0)*65 + ww], st[(cc+1)*65 + ww],
                                   st[(cc+2)*65 + ww], st[(cc+3)*65 + ww]);
            *(float4*)(dst + 4*j) = v;
        }
        __syncthreads();
    }
}

// ======================================================================
// Scan kernel v5: tensor-core GRU, 12 warps (384 thr), 32 gates/warp,
// W fragments for k-chunks 0..5 cached in registers (ldsm only ch 6,7).
// ======================================================================
#define W_OFF_LO 104448
#define H_OFF_HI 208896
#define H_OFF_LO 211072
#define SG_OFF   213248
#define SCAN_SMEM (SG_OFF + 384*9*4)   // 227,072 bytes

__global__ void __launch_bounds__(384, 1)
scan_kernel(const float* __restrict__ whh_h,
            const float* __restrict__ bhh_h,
            const float* __restrict__ whh_w,
            const float* __restrict__ bhh_w,
            const float* __restrict__ gxh,
            const float* __restrict__ gxw,
            float* __restrict__ ohp,
            float* __restrict__ owp)
{
    extern __shared__ char smraw[];
    __nv_bfloat16* w_hi = (__nv_bfloat16*)(smraw);              // [384][136]
    __nv_bfloat16* w_lo = (__nv_bfloat16*)(smraw + W_OFF_LO);
    __nv_bfloat16* h_hi = (__nv_bfloat16*)(smraw + H_OFF_HI);   // [8][136]
    __nv_bfloat16* h_lo = (__nv_bfloat16*)(smraw + H_OFF_LO);
    float* sg = (float*)(smraw + SG_OFF);                       // [384][9]

    const uint32_t sbase = smem_u32(smraw);
    const uint32_t u_w_hi = sbase;
    const uint32_t u_w_lo = sbase + W_OFF_LO;
    const uint32_t u_h_hi = sbase + H_OFF_HI;
    const uint32_t u_h_lo = sbase + H_OFF_LO;

    const int dir = blockIdx.x >> 6;
    const int sub = blockIdx.x & 63;
    const int b   = sub >> 3;
    const int q0  = (sub & 7) << 3;

    const float* whh = dir ? whh_w : whh_h;
    const float* bhh = dir ? bhh_w : bhh_h;
    const float* gx  = dir ? gxw : gxh;
    float* outp      = dir ? owp : ohp;

    const int tid  = threadIdx.x;
    const int lane = tid & 31;
    const int wrp  = tid >> 5;          // 0..11, gate base = wrp*32

    // ---- stage W hi/lo ----
    {
        const int col4 = lane * 4;
#pragma unroll
        for (int j = 0; j < 32; j++) {
            int r = wrp * 32 + j;
            float4 v = *(const float4*)(whh + (size_t)r * 128 + col4);
            uint2 hi, lo; cvt4(v, hi, lo);
            *(uint2*)(w_hi + r * SA_STRIDE + col4) = hi;
            *(uint2*)(w_lo + r * SA_STRIDE + col4) = lo;
        }
    }
    // ---- zero h bufs ----
    for (int i = tid; i < 8 * SA_STRIDE; i += 384) {
        h_hi[i] = __ushort_as_bfloat16((unsigned short)0);
        h_lo[i] = __ushort_as_bfloat16((unsigned short)0);
    }

    // ---- tail-role setup (tid < 256): 4 seqs/thread ----
    const int c  = tid & 127;
    const int sh = (tid >> 7) & 1;
    float hreg[4];
    float bh_r = 0.f, bh_z = 0.f, bh_n = 0.f;
    if (tid < 256) {
#pragma unroll
        for (int j = 0; j < 4; j++) hreg[j] = 0.f;
        bh_r = bhh[c];
        bh_z = bhh[c + 128];
        bh_n = bhh[c + 256];
    }
    __syncthreads();

#define PIXAT(t, s2) (dir ? ((b*64 + q0+(s2))*64 + (t)) : ((b*64 + (t))*64 + q0+(s2)))

    const uint32_t a_off0 = (uint32_t)(((wrp*32 + (lane & 15)) * SA_STRIDE
                                        + ((lane >> 4) << 3)) * 2);
    const uint32_t b_off  = (uint32_t)((((lane & 7) * SA_STRIDE)
                                        + (((lane >> 3) & 1) << 3)) * 2);
    const int grow = wrp*32 + (lane >> 2);
    const int scol = (lane & 3) * 2;

    // ---- preload W fragments for k-chunks 0..5 into registers ----
    uint32_t wfh[2][6][4], wfl[2][6][4];
#pragma unroll
    for (int i = 0; i < 2; i++)
#pragma unroll
        for (int ch = 0; ch < 6; ch++) {
            uint32_t off = a_off0 + (uint32_t)(i * 16 * SA_STRIDE * 2) + (uint32_t)(ch * 32);
            ldsm4(wfh[i][ch], u_w_hi + off);
            ldsm4(wfl[i][ch], u_w_lo + off);
        }

    for (int t = 0; t < 64; t++) {
        float gr[4], gz[4], gn[4];
        if (tid < 256) {
#pragma unroll
            for (int j = 0; j < 4; j++) {
                const float* base = gx + (size_t)PIXAT(t, sh*4 + j) * K3;
                gr[j] = base[c];
                gz[j] = base[128 + c];
                gn[j] = base[256 + c];
            }
        }

        // ---- mma phase: 2 m16 tiles per warp, W mostly register-resident ----
        float acc[2][4];
#pragma unroll
        for (int i = 0; i < 2; i++)
#pragma unroll
            for (int e = 0; e < 4; e++) acc[i][e] = 0.f;

#pragma unroll
        for (int ch = 0; ch < 8; ch++) {
            const uint32_t kb = (uint32_t)(ch * 32);
            uint32_t bh2[2], bl2[2];
            ldsm2(bh2, u_h_hi + b_off + kb);
            ldsm2(bl2, u_h_lo + b_off + kb);
            uint32_t at[2][4], alt[2][4];
            if (ch >= 6) {
#pragma unroll
                for (int i = 0; i < 2; i++) {
                    uint32_t off = a_off0 + (uint32_t)(i * 16 * SA_STRIDE * 2) + kb;
                    ldsm4(at[i], u_w_hi + off);
                    ldsm4(alt[i], u_w_lo + off);
                }
            }
#pragma unroll
            for (int i = 0; i < 2; i++) {
                const uint32_t* A_h = (ch < 6) ? wfh[i][ch] : at[i];
                const uint32_t* A_l = (ch < 6) ? wfl[i][ch] : alt[i];
                mma16816(acc[i], A_h, bh2);
                mma16816(acc[i], A_h, bl2);
                mma16816(acc[i], A_l, bh2);
            }
        }

        // scalar sg stores (stride-9 rows: no vector stores!)
#pragma unroll
        for (int i = 0; i < 2; i++) {
            int g = grow + i*16;
            sg[g*9 + scol]         = acc[i][0];
            sg[g*9 + scol + 1]     = acc[i][1];
            sg[(g+8)*9 + scol]     = acc[i][2];
            sg[(g+8)*9 + scol + 1] = acc[i][3];
        }
        __syncthreads();

        // ---- tail: nonlinearity + h update (4 seqs/thread) ----
        if (tid < 256) {
#pragma unroll
            for (int j = 0; j < 4; j++) {
                int s2 = sh*4 + j;
                float rp = sg[c*9 + s2]       + bh_r + gr[j];
                float zp = sg[(c+128)*9 + s2] + bh_z + gz[j];
                float sn = sg[(c+256)*9 + s2] + bh_n;
                float er = __expf(-rp);
                float ez = __expf(-zp);
                float r = __fdividef(1.f, 1.f + er);
                float z = __fdividef(1.f, 1.f + ez);
                float xn = gn[j] + r * sn;
                float en = __expf(2.f * xn);
                float n = 1.f - __fdividef(2.f, en + 1.f);
                float hnew = (1.f - z) * n + z * hreg[j];
                hreg[j] = hnew;
                unsigned short hb = __bfloat16_as_ushort(__float2bfloat16(hnew));
                float lr = hnew - __uint_as_float((uint32_t)hb << 16);
                unsigned short lb = __bfloat16_as_ushort(__float2bfloat16(lr));
                h_hi[s2 * SA_STRIDE + c] = __ushort_as_bfloat16(hb);
                h_lo[s2 * SA_STRIDE + c] = __ushort_as_bfloat16(lb);
                outp[(size_t)PIXAT(t, s2) * DIMC + c] = hnew;
            }
        }
        __syncthreads();
    }
#undef PIXAT
}

// ======================================================================
// Tail kernel (bf16x3 tensor-core, unchanged from R9 passing version)
// ======================================================================
#define TAILM_SMEM 139264

__global__ void __launch_bounds__(256)
tail_kernel(const float* __restrict__ ohp,
            const float* __restrict__ owp,
            const float* __restrict__ xres,
            const float* __restrict__ gate_w,
            const float* __restrict__ gate_b,
            const float* __restrict__ pw,
            const float* __restrict__ pscale,
            const float* __restrict__ pshift,
            float* __restrict__ out)
{
    extern __shared__ char smraw[];
    __nv_bfloat16* a_hi = (__nv_bfloat16*)(smraw);
    __nv_bfloat16* a_lo = (__nv_bfloat16*)(smraw + 34816);
    __nv_bfloat16* b_hi = (__nv_bfloat16*)(smraw + 69632);
    __nv_bfloat16* b_lo = (__nv_bfloat16*)(smraw + 104448);
    float* st = (float*)(smraw + 69632);
    const uint32_t sbase = smem_u32(smraw);
    const uint32_t u_a_hi = sbase;
    const uint32_t u_a_lo = sbase + 34816;
    const uint32_t u_b_hi = sbase + 69632;
    const uint32_t u_b_lo = sbase + 104448;

    const int m0  = blockIdx.x * 128;
    const int b   = m0 >> 12;
    const int hw0 = m0 & 4095;
    const int tid = threadIdx.x;
    const int wid = tid >> 5;
    const int lane = tid & 31;
    const int wm = wid >> 1;
    const int wn = wid & 1;
    const int gid = lane >> 2, tig = lane & 3;
    const int col4 = lane * 4;
    const int rbase = wid;

#pragma unroll
    for (int j = 0; j < 16; j++) {
        int r = rbase + 8 * j;
        float4 a = *(const float4*)(ohp + (size_t)(m0 + r) * DIMC + col4);
        float4 c = *(const float4*)(owp + (size_t)(m0 + r) * DIMC + col4);
        float4 v = make_float4(a.x + c.x, a.y + c.y, a.z + c.z, a.w + c.w);
        uint2 hi, lo; cvt4(v, hi, lo);
        *(uint2*)(a_hi + r * SA_STRIDE + col4) = hi;
        *(uint2*)(a_lo + r * SA_STRIDE + col4) = lo;
        float4 w = *(const float4*)(gate_w + (size_t)r * 128 + col4);
        cvt4(w, hi, lo);
        *(uint2*)(b_hi + r * SA_STRIDE + col4) = hi;
        *(uint2*)(b_lo + r * SA_STRIDE + col4) = lo;
    }
    __syncthreads();

    const uint32_t a_off0 = (uint32_t)(((wm*32 + (lane & 15)) * SA_STRIDE
                                        + ((lane >> 4) << 3)) * 2);
    const uint32_t b_row0 = (uint32_t)(wn*64 + (lane & 7) + ((lane >> 4) << 3));
    const uint32_t b_col8 = (uint32_t)(((lane >> 3) & 1) << 3);

    // GEMM1
    float acc[2][8][4];
#pragma unroll
    for (int i = 0; i < 2; i++)
#pragma unroll
        for (int j = 0; j < 8; j++)
#pragma unroll
            for (int e = 0; e < 4; e++) acc[i][j][e] = 0.f;

#pragma unroll
    for (int ch = 0; ch < 8; ch++) {
        const int k = ch * 16;
        uint32_t ah[2][4], al[2][4];
#pragma unroll
        for (int i = 0; i < 2; i++) {
            uint32_t off = a_off0 + (uint32_t)((i*16*SA_STRIDE + k) * 2);
            ldsm4(ah[i], u_a_hi + off);
            ldsm4(al[i], u_a_lo + off);
        }
        uint32_t bh[8][2], bl[8][2];
#pragma unroll
        for (int nb = 0; nb < 4; nb++) {
            uint32_t off = (uint32_t)(((b_row0 + nb*16) * SA_STRIDE + k + b_col8) * 2);
            uint32_t r[4];
            ldsm4(r, u_b_hi + off);
            bh[2*nb][0] = r[0]; bh[2*nb][1] = r[1];
            bh[2*nb+1][0] = r[2]; bh[2*nb+1][1] = r[3];
            ldsm4(r, u_b_lo + off);
            bl[2*nb][0] = r[0]; bl[2*nb][1] = r[1];
            bl[2*nb+1][0] = r[2]; bl[2*nb+1][1] = r[3];
        }
#pragma unroll
        for (int i = 0; i < 2; i++)
#pragma unroll
            for (int j = 0; j < 8; j++) {
                mma16816(acc[i][j], ah[i], bh[j]);
                mma16816(acc[i][j], ah[i], bl[j]);
                mma16816(acc[i][j], al[i], bh[j]);
            }
    }
    __syncthreads();

    // gated = s * sigmoid(gate+gb); overwrite A; stage pw in B
#pragma unroll
    for (int i = 0; i < 2; i++) {
        int mrow = wm*32 + i*16 + gid;
#pragma unroll
        for (int j = 0; j < 8; j++) {
            int ncol = wn*64 + j*8 + tig*2;
            float2 gb2 = *(const float2*)(gate_b + ncol);
#pragma unroll
            for (int rr = 0; rr < 2; rr++) {
                int m = mrow + rr*8;
#pragma unroll
                for (int e = 0; e < 2; e++) {
                    int n = ncol + e;
                    float gv = acc[i][j][rr*2 + e] + (e ? gb2.y : gb2.x);
                    float sig = __fdividef(1.f, 1.f + __expf(-gv));
                    float sval = __bfloat162float(a_hi[m*SA_STRIDE + n])
                               + __bfloat162float(a_lo[m*SA_STRIDE + n]);
                    float gt = sval * sig;
                    unsigned short hb = __bfloat16_as_ushort(__float2bfloat16(gt));
                    float lr = gt - __uint_as_float((uint32_t)hb << 16);
                    unsigned short lb = __bfloat16_as_ushort(__float2bfloat16(lr));
                    a_hi[m*SA_STRIDE + n] = __ushort_as_bfloat16(hb);
                    a_lo[m*SA_STRIDE + n] = __ushort_as_bfloat16(lb);
                }
            }
        }
    }
#pragma unroll
    for (int j = 0; j < 16; j++) {
        int r = rbase + 8 * j;
        float4 w = *(const float4*)(pw + (size_t)r * 128 + col4);
        uint2 hi, lo; cvt4(w, hi, lo);
        *(uint2*)(b_hi + r * SA_STRIDE + col4) = hi;
        *(uint2*)(b_lo + r * SA_STRIDE + col4) = lo;
    }
    __syncthreads();

    // GEMM2
    float acc2[2][8][4];
#pragma unroll
    for (int i = 0; i < 2; i++)
#pragma unroll
        for (int j = 0; j < 8; j++)
#pragma unroll
            for (int e = 0; e < 4; e++) acc2[i][j][e] = 0.f;

#pragma unroll
    for (int ch = 0; ch < 8; ch++) {
        const int k = ch * 16;
        uint32_t ah[2][4], al[2][4];
#pragma unroll
        for (int i = 0; i < 2; i++) {
            uint32_t off = a_off0 + (uint32_t)((i*16*SA_STRIDE + k) * 2);
            ldsm4(ah[i], u_a_hi + off);
            ldsm4(al[i], u_a_lo + off);
        }
        uint32_t bh[8][2], bl[8][2];
#pragma unroll
        for (int nb = 0; nb < 4; nb++) {
            uint32_t off = (uint32_t)(((b_row0 + nb*16) * SA_STRIDE + k + b_col8) * 2);
            uint32_t r[4];
            ldsm4(r, u_b_hi + off);
            bh[2*nb][0] = r[0]; bh[2*nb][1] = r[1];
            bh[2*nb+1][0] = r[2]; bh[2*nb+1][1] = r[3];
            ldsm4(r, u_b_lo + off);
            bl[2*nb][0] = r[0]; bl[2*nb][1] = r[1];
            bl[2*nb+1][0] = r[2]; bl[2*nb+1][1] = r[3];
        }
#pragma unroll
        for (int i = 0; i < 2; i++)
#pragma unroll
            for (int j = 0; j < 8; j++) {
                mma16816(acc2[i][j], ah[i], bh[j]);
                mma16816(acc2[i][j], ah[i], bl[j]);
                mma16816(acc2[i][j], al[i], bh[j]);
            }
    }
    __syncthreads();

    // epilogue
#pragma unroll
    for (int i = 0; i < 2; i++) {
        int mrow = wm*32 + i*16 + gid;
#pragma unroll
        for (int j = 0; j < 8; j++) {
            int ncol = wn*64 + j*8 + tig*2;
            float2 q0 = *(const float2*)(pscale + ncol);
            float2 q1 = *(const float2*)(pshift + ncol);
#pragma unroll
            for (int rr = 0; rr < 2; rr++) {
                int m = mrow + rr*8;
                float2 xr = *(const float2*)(xres + (size_t)(m0 + m) * DIMC + ncol);
                float v0 = fmaxf(fmaf(acc2[i][j][rr*2+0], q0.x, q1.x), 0.f) + xr.x;
                float v1 = fmaxf(fmaf(acc2[i][j][rr*2+1], q0.y, q1.y), 0.f) + xr.y;
                st[(ncol+0)*132 + m] = v0;
                st[(ncol+1)*132 + m] = v1;
            }
        }
    }
    __syncthreads();

    for (int i = tid; i < 128*128; i += 256) {
        int cc = i >> 7, p = i & 127;
        out[(size_t)(b*128 + cc)*HW + hw0 + p] = st[cc*132 + p];
    }
}

// ======================================================================
// Launch
// ======================================================================
extern "C" void kernel_launch(void* const* d_in, const int* in_sizes, int n_in,
                              void* d_out, int out_size)
{
    const float* l     = (const float*)d_in[0];
    const float* m_    = (const float*)d_in[1];
    const float* s_    = (const float*)d_in[2];
    const float* piw   = (const float*)d_in[3];
    const float* pisc  = (const float*)d_in[4];
    const float* pish  = (const float*)d_in[5];
    const float* wih_h = (const float*)d_in[6];
    const float* whh_h = (const float*)d_in[7];
    const float* bih_h = (const float*)d_in[8];
    const float* bhh_h = (const float*)d_in[9];
    const float* wih_w = (const float*)d_in[10];
    const float* whh_w = (const float*)d_in[11];
    const float* bih_w = (const float*)d_in[12];
    const float* bhh_w = (const float*)d_in[13];
    const float* gw    = (const float*)d_in[14];
    const float* gb    = (const float*)d_in[15];
    const float* pow_  = (const float*)d_in[16];
    const float* posc  = (const float*)d_in[17];
    const float* posh  = (const float*)d_in[18];
    float* out = (float*)d_out;

    void *p_xcat, *p_x, *p_gxh, *p_gxw, *p_oh, *p_ow;
    cudaGetSymbolAddress(&p_xcat, g_xcat);
    cudaGetSymbolAddress(&p_x,    g_x);
    cudaGetSymbolAddress(&p_gxh,  g_gxh);
    cudaGetSymbolAddress(&p_gxw,  g_gxw);
    cudaGetSymbolAddress(&p_oh,   g_oh);
    cudaGetSymbolAddress(&p_ow,   g_ow);
    float* xcat = (float*)p_xcat;
    float* x    = (float*)p_x;
    float* gxh  = (float*)p_gxh;
    float* gxw  = (float*)p_gxw;
    float* oh   = (float*)p_oh;
    float* ow   = (float*)p_ow;

    cudaFuncSetAttribute(fused_projgx_kernel, cudaFuncAttributeMaxDynamicSharedMemorySize, MMA_SMEM);
    cudaFuncSetAttribute(scan_kernel, cudaFuncAttributeMaxDynamicSharedMemorySize, SCAN_SMEM);
    cudaFuncSetAttribute(tail_kernel, cudaFuncAttributeMaxDynamicSharedMemorySize, TAILM_SMEM);

    // 1. resize + concat
    resize_concat_kernel<<<BATCH*HGT, 256>>>(l, m_, s_, xcat);

    // 2+3. proj_in + gx (fused, A staged once, occ 2)
    fused_projgx_kernel<<<M_TOT/128, 256, MMA_SMEM>>>(
        xcat, piw, pisc, pish, x, wih_h, bih_h, wih_w, bih_w, gxh, gxw);

    // 4. both GRU scans (12 warps, register-cached W frags)
    scan_kernel<<<128, 384, SCAN_SMEM>>>(whh_h, bhh_h, whh_w, bhh_w, gxh, gxw, oh, ow);

    // 5. gate + proj_out + residual (bf16x3 tensor-core) + transposed store
    tail_kernel<<<M_TOT/128, 256, TAILM_SMEM>>>(oh, ow, x, gw, gb, pow_, posc, posh, out);
}